// round 8
// baseline (speedup 1.0000x reference)
#include <cuda_runtime.h>
#include <cuda_bf16.h>
#include <mma.h>
#include <cstdint>

using namespace nvcuda;

#define SEQ    4096
#define DMODEL 1024
#define HEADS  16
#define DHEAD  64

// ---------------- scratch (no cudaMalloc allowed) ----------------
__device__ float g_q[SEQ * DMODEL];
__device__ float g_k[SEQ * DMODEL];
__device__ float g_v[SEQ * DMODEL];
__device__ float g_at[SEQ * DMODEL];

__device__ __nv_bfloat16 g_xh[SEQ * DMODEL];
__device__ __nv_bfloat16 g_xl[SEQ * DMODEL];
__device__ __nv_bfloat16 g_ath[SEQ * DMODEL];
__device__ __nv_bfloat16 g_atl[SEQ * DMODEL];
__device__ __nv_bfloat16 g_qh[SEQ * DMODEL];
__device__ __nv_bfloat16 g_ql[SEQ * DMODEL];
__device__ __nv_bfloat16 g_kh[SEQ * DMODEL];
__device__ __nv_bfloat16 g_kl[SEQ * DMODEL];
__device__ __nv_bfloat16 g_vh[SEQ * DMODEL];
__device__ __nv_bfloat16 g_vl[SEQ * DMODEL];
__device__ __nv_bfloat16 g_wqh[DMODEL * DMODEL];
__device__ __nv_bfloat16 g_wql[DMODEL * DMODEL];
__device__ __nv_bfloat16 g_wkh[DMODEL * DMODEL];
__device__ __nv_bfloat16 g_wkl[DMODEL * DMODEL];
__device__ __nv_bfloat16 g_wvh[DMODEL * DMODEL];
__device__ __nv_bfloat16 g_wvl[DMODEL * DMODEL];
__device__ __nv_bfloat16 g_woh[DMODEL * DMODEL];
__device__ __nv_bfloat16 g_wol[DMODEL * DMODEL];

__device__ __forceinline__ unsigned pk2(float a, float b) {
    __nv_bfloat162 t = __floats2bfloat162_rn(a, b);
    return *reinterpret_cast<unsigned*>(&t);
}

__device__ __forceinline__ uint32_t smem_u32(const void* p) {
    uint32_t a;
    asm("{ .reg .u64 t; cvta.to.shared.u64 t, %1; cvt.u32.u64 %0, t; }"
        : "=r"(a) : "l"(p));
    return a;
}

// ---------------- prep kernels ----------------
__global__ void __launch_bounds__(256) split_kernel(
    const float* __restrict__ src, __nv_bfloat16* __restrict__ hi,
    __nv_bfloat16* __restrict__ lo, float scale)
{
    int i = blockIdx.x * 256 + threadIdx.x;
    float4 v = reinterpret_cast<const float4*>(src)[i];
    v.x *= scale; v.y *= scale; v.z *= scale; v.w *= scale;
    __nv_bfloat16 h0 = __float2bfloat16_rn(v.x);
    __nv_bfloat16 h1 = __float2bfloat16_rn(v.y);
    __nv_bfloat16 h2 = __float2bfloat16_rn(v.z);
    __nv_bfloat16 h3 = __float2bfloat16_rn(v.w);
    float r0 = v.x - __bfloat162float(h0);
    float r1 = v.y - __bfloat162float(h1);
    float r2 = v.z - __bfloat162float(h2);
    float r3 = v.w - __bfloat162float(h3);
    uint2 hv, lv;
    __nv_bfloat162 hh0 = {h0, h1}, hh1 = {h2, h3};
    hv.x = *reinterpret_cast<unsigned*>(&hh0);
    hv.y = *reinterpret_cast<unsigned*>(&hh1);
    lv.x = pk2(r0, r1);
    lv.y = pk2(r2, r3);
    reinterpret_cast<uint2*>(hi)[i] = hv;
    reinterpret_cast<uint2*>(lo)[i] = lv;
}

__global__ void __launch_bounds__(256) wsplit_kernel(
    const float* __restrict__ W0, const float* __restrict__ W1,
    const float* __restrict__ W2, const float* __restrict__ W3,
    __nv_bfloat16* H0, __nv_bfloat16* L0, __nv_bfloat16* H1, __nv_bfloat16* L1,
    __nv_bfloat16* H2, __nv_bfloat16* L2, __nv_bfloat16* H3, __nv_bfloat16* L3)
{
    const int z = blockIdx.z;
    const float* W = (z == 0) ? W0 : (z == 1) ? W1 : (z == 2) ? W2 : W3;
    __nv_bfloat16* H = (z == 0) ? H0 : (z == 1) ? H1 : (z == 2) ? H2 : H3;
    __nv_bfloat16* L = (z == 0) ? L0 : (z == 1) ? L1 : (z == 2) ? L2 : L3;

    __shared__ float ts[32][33];
    const int n0 = blockIdx.x * 32, k0 = blockIdx.y * 32;
    const int tx = threadIdx.x, ty = threadIdx.y;
#pragma unroll
    for (int r = 0; r < 4; r++)
        ts[ty + 8 * r][tx] = W[(size_t)(k0 + ty + 8 * r) * DMODEL + n0 + tx];
    __syncthreads();
#pragma unroll
    for (int r = 0; r < 4; r++) {
        int n = n0 + ty + 8 * r;
        float a = ts[tx][ty + 8 * r];
        __nv_bfloat16 h = __float2bfloat16_rn(a);
        H[(size_t)n * DMODEL + k0 + tx] = h;
        L[(size_t)n * DMODEL + k0 + tx] = __float2bfloat16_rn(a - __bfloat162float(h));
    }
}

// ---------------- WMMA split-bf16 GEMM (unchanged from R3) ----------------
#define LDM 40

__global__ void __launch_bounds__(256) gemm_wmma(
    const __nv_bfloat16* __restrict__ Ah, const __nv_bfloat16* __restrict__ Al,
    const __nv_bfloat16* __restrict__ Bh0, const __nv_bfloat16* __restrict__ Bl0,
    const __nv_bfloat16* __restrict__ Bh1, const __nv_bfloat16* __restrict__ Bl1,
    const __nv_bfloat16* __restrict__ Bh2, const __nv_bfloat16* __restrict__ Bl2,
    float* C0, float* C1, float* C2)
{
    const int z = blockIdx.z;
    const __nv_bfloat16* Bh = (z == 0) ? Bh0 : (z == 1) ? Bh1 : Bh2;
    const __nv_bfloat16* Bl = (z == 0) ? Bl0 : (z == 1) ? Bl1 : Bl2;
    float* C = (z == 0) ? C0 : (z == 1) ? C1 : C2;

    __shared__ __nv_bfloat16 As[2][128 * LDM];
    __shared__ __nv_bfloat16 Bs[2][128 * LDM];

    const int tid = threadIdx.x;
    const int wid = tid >> 5;
    const int wm = wid & 3;
    const int wn = wid >> 2;
    const int m0 = blockIdx.y * 128;
    const int n0 = blockIdx.x * 128;

    wmma::fragment<wmma::accumulator, 16, 16, 16, float> acc[2][4];
#pragma unroll
    for (int i = 0; i < 2; i++)
#pragma unroll
        for (int j = 0; j < 4; j++) wmma::fill_fragment(acc[i][j], 0.0f);

    const int r  = tid >> 2;
    const int ch = tid & 3;

    for (int kc = 0; kc < DMODEL; kc += 32) {
#pragma unroll
        for (int hf = 0; hf < 2; hf++) {
            const int row = r + hf * 64;
            const size_t go = (size_t)row * DMODEL + kc + ch * 8;
            const int so = row * LDM + ch * 8;
            *reinterpret_cast<uint4*>(&As[0][so]) =
                *reinterpret_cast<const uint4*>(&Ah[(size_t)m0 * DMODEL + go]);
            *reinterpret_cast<uint4*>(&As[1][so]) =
                *reinterpret_cast<const uint4*>(&Al[(size_t)m0 * DMODEL + go]);
            *reinterpret_cast<uint4*>(&Bs[0][so]) =
                *reinterpret_cast<const uint4*>(&Bh[(size_t)n0 * DMODEL + go]);
            *reinterpret_cast<uint4*>(&Bs[1][so]) =
                *reinterpret_cast<const uint4*>(&Bl[(size_t)n0 * DMODEL + go]);
        }
        __syncthreads();

#pragma unroll
        for (int ks = 0; ks < 32; ks += 16) {
            wmma::fragment<wmma::matrix_a, 16, 16, 16, __nv_bfloat16,
                           wmma::row_major> ah[2], al[2];
#pragma unroll
            for (int i = 0; i < 2; i++) {
                wmma::load_matrix_sync(ah[i], &As[0][(wm * 32 + 16 * i) * LDM + ks], LDM);
                wmma::load_matrix_sync(al[i], &As[1][(wm * 32 + 16 * i) * LDM + ks], LDM);
            }
#pragma unroll
            for (int j = 0; j < 4; j++) {
                wmma::fragment<wmma::matrix_b, 16, 16, 16, __nv_bfloat16,
                               wmma::col_major> bh, bl;
                wmma::load_matrix_sync(bh, &Bs[0][(wn * 64 + 16 * j) * LDM + ks], LDM);
                wmma::load_matrix_sync(bl, &Bs[1][(wn * 64 + 16 * j) * LDM + ks], LDM);
#pragma unroll
                for (int i = 0; i < 2; i++) {
                    wmma::mma_sync(acc[i][j], ah[i], bh, acc[i][j]);
                    wmma::mma_sync(acc[i][j], ah[i], bl, acc[i][j]);
                    wmma::mma_sync(acc[i][j], al[i], bh, acc[i][j]);
                }
            }
        }
        __syncthreads();
    }

#pragma unroll
    for (int i = 0; i < 2; i++)
#pragma unroll
        for (int j = 0; j < 4; j++)
            wmma::store_matrix_sync(
                &C[(size_t)(m0 + wm * 32 + 16 * i) * DMODEL + n0 + wn * 64 + 16 * j],
                acc[i][j], DMODEL, wmma::mem_row_major);
}

__global__ void __launch_bounds__(256) bias_add(
    float* __restrict__ out, const float* __restrict__ bo)
{
    int i = blockIdx.x * 256 + threadIdx.x;
    float4 v = reinterpret_cast<float4*>(out)[i];
    float4 b = *reinterpret_cast<const float4*>(&bo[(i * 4) & (DMODEL - 1)]);
    v.x += b.x; v.y += b.y; v.z += b.z; v.w += b.w;
    reinterpret_cast<float4*>(out)[i] = v;
}

// ---------------- cp.async flash attention (pre-split bf16 inputs) ----------------
// CTA = 128 query rows x 1 head. K/V tiles arrive pre-split (hi/lo bf16) via
// cp.async into a 2-stage smem ring; ONE __syncthreads per 64-key tile, copy of
// tile j+1 overlaps compute of tile j. Compute = R6 register-resident mma.sync.
#define LP 72            // bf16 pitch (144B rows) -> ldmatrix conflict-free
#define ST_KH 0
#define ST_KL 9216
#define ST_VH 18432
#define ST_VL 27648
#define STAGE 36864      // bytes per stage (4 sub-buffers)
#define ATTN_SMEM (2 * STAGE)   // 73728

__device__ __forceinline__ void ldsm_x4(uint32_t* r, uint32_t addr) {
    asm volatile("ldmatrix.sync.aligned.m8n8.x4.shared.b16 {%0,%1,%2,%3}, [%4];"
        : "=r"(r[0]), "=r"(r[1]), "=r"(r[2]), "=r"(r[3]) : "r"(addr));
}
__device__ __forceinline__ void ldsm_x4_t(uint32_t* r, uint32_t addr) {
    asm volatile("ldmatrix.sync.aligned.m8n8.x4.trans.shared.b16 {%0,%1,%2,%3}, [%4];"
        : "=r"(r[0]), "=r"(r[1]), "=r"(r[2]), "=r"(r[3]) : "r"(addr));
}
__device__ __forceinline__ void mma16816(float* c, const uint32_t* a,
                                         const uint32_t* b) {
    asm volatile("mma.sync.aligned.m16n8k16.row.col.f32.bf16.bf16.f32 "
        "{%0,%1,%2,%3}, {%4,%5,%6,%7}, {%8,%9}, {%0,%1,%2,%3};"
        : "+f"(c[0]), "+f"(c[1]), "+f"(c[2]), "+f"(c[3])
        : "r"(a[0]), "r"(a[1]), "r"(a[2]), "r"(a[3]), "r"(b[0]), "r"(b[1]));
}
__device__ __forceinline__ void cp16(uint32_t saddr, const void* g) {
    asm volatile("cp.async.ca.shared.global [%0], [%1], 16;"
                 :: "r"(saddr), "l"(g) : "memory");
}
#define CP_COMMIT() asm volatile("cp.async.commit_group;" ::: "memory")
#define CP_WAIT0()  asm volatile("cp.async.wait_group 0;" ::: "memory")

__device__ __forceinline__ void split_pack(float a, float b,
                                           uint32_t& h, uint32_t& l)
{
    __nv_bfloat16 ha = __float2bfloat16_rn(a);
    __nv_bfloat16 hb = __float2bfloat16_rn(b);
    __nv_bfloat162 hh = {ha, hb};
    h = *reinterpret_cast<unsigned*>(&hh);
    l = pk2(a - __bfloat162float(ha), b - __bfloat162float(hb));
}

__device__ __forceinline__ void prefetch_kv(
    uint32_t stg,
    const __nv_bfloat16* __restrict__ kh, const __nv_bfloat16* __restrict__ kl,
    const __nv_bfloat16* __restrict__ vh, const __nv_bfloat16* __restrict__ vl,
    int j64, int hoff, int tid)
{
    const int rb = tid >> 3;           // 0..31
    const int ch = tid & 7;
#pragma unroll
    for (int half = 0; half < 2; half++) {
        const int r = rb + 32 * half;
        const size_t go = (size_t)(j64 + r) * DMODEL + hoff + ch * 8;
        const uint32_t so = stg + (uint32_t)(r * 144 + ch * 16);
        cp16(so + ST_KH, kh + go);
        cp16(so + ST_KL, kl + go);
        cp16(so + ST_VH, vh + go);
        cp16(so + ST_VL, vl + go);
    }
}

__global__ void __launch_bounds__(256) attn_cp(
    const __nv_bfloat16* __restrict__ qh_g, const __nv_bfloat16* __restrict__ ql_g,
    const __nv_bfloat16* __restrict__ kh_g, const __nv_bfloat16* __restrict__ kl_g,
    const __nv_bfloat16* __restrict__ vh_g, const __nv_bfloat16* __restrict__ vl_g,
    float* __restrict__ outg)
{
    extern __shared__ char smc[];
    const int tid  = threadIdx.x;
    const int w    = tid >> 5;
    const int lane = tid & 31;
    const int h    = blockIdx.y;
    const int ib   = (int)(gridDim.x - 1u - blockIdx.x);  // heavy first
    const int row0 = ib * 128;
    const int hoff = h * DHEAD;
    const uint32_t smb = smem_u32(smc);

    // -------- stage Q (pre-scaled, pre-split bf16) through stage0 --------
    {
#pragma unroll
        for (int u = 0; u < 4; u++) {
            const int chunk = tid + 256 * u;       // 0..1023
            const int r = chunk >> 3, ch = chunk & 7;
            const size_t go = (size_t)(row0 + r) * DMODEL + hoff + ch * 8;
            *reinterpret_cast<uint4*>(smc + r * 144 + ch * 16) =
                *reinterpret_cast<const uint4*>(qh_g + go);
            *reinterpret_cast<uint4*>(smc + 18432 + r * 144 + ch * 16) =
                *reinterpret_cast<const uint4*>(ql_g + go);
        }
    }
    __syncthreads();

    // -------- persistent Q A-fragments --------
    uint32_t qh[4][4], ql[4][4];
    {
        const int qrow = w * 16 + (lane & 15);
        const int csel = (lane >> 4) * 8;
#pragma unroll
        for (int kt = 0; kt < 4; kt++) {
            uint32_t ah = smb + (uint32_t)((qrow * LP + kt * 16 + csel) * 2);
            ldsm_x4(qh[kt], ah);
            ldsm_x4(ql[kt], ah + 18432);
        }
    }
    __syncthreads();   // Q frags in regs before stage0 is overwritten

    float o[8][4];
#pragma unroll
    for (int nt = 0; nt < 8; nt++)
#pragma unroll
        for (int j = 0; j < 4; j++) o[nt][j] = 0.f;
    float m0 = -1e30f, m1 = -1e30f, l0 = 0.f, l1 = 0.f;

    const int r0g = row0 + w * 16 + (lane >> 2);
    const int jmax = 2 * ib + 1;

    // preload tile 0 into stage 0
    prefetch_kv(smb, kh_g, kl_g, vh_g, vl_g, 0, hoff, tid);
    CP_COMMIT();

    for (int jb = 0; jb <= jmax; jb++) {
        const uint32_t stg = smb + (uint32_t)((jb & 1) * STAGE);
        CP_WAIT0();
        __syncthreads();   // tile jb visible to all; compute(jb-1) finished
        if (jb < jmax) {
            prefetch_kv(smb + (uint32_t)(((jb + 1) & 1) * STAGE),
                        kh_g, kl_g, vh_g, vl_g, (jb + 1) * 64, hoff, tid);
            CP_COMMIT();
        }

        if (jb * 64 <= row0 + w * 16 + 15) {     // warp-uniform causal skip
            // -------- S = Q.K^T --------
            float c[8][4];
#pragma unroll
            for (int nt = 0; nt < 8; nt++)
#pragma unroll
                for (int j = 0; j < 4; j++) c[nt][j] = 0.f;

            const int kkey = (lane >> 4) * 8 + (lane & 7);
            const int kcol = ((lane >> 3) & 1) * 8;
#pragma unroll
            for (int kt = 0; kt < 4; kt++) {
#pragma unroll
                for (int ntp = 0; ntp < 4; ntp++) {
                    uint32_t bh[4], bl[4];
                    uint32_t ka = stg + (uint32_t)(((ntp * 16 + kkey) * LP +
                                                   kt * 16 + kcol) * 2);
                    ldsm_x4(bh, ka + ST_KH);
                    ldsm_x4(bl, ka + ST_KL);
                    mma16816(c[2 * ntp],     qh[kt], bh);
                    mma16816(c[2 * ntp],     qh[kt], bl);
                    mma16816(c[2 * ntp],     ql[kt], bh);
                    mma16816(c[2 * ntp + 1], qh[kt], bh + 2);
                    mma16816(c[2 * ntp + 1], qh[kt], bl + 2);
                    mma16816(c[2 * ntp + 1], ql[kt], bh + 2);
                }
            }

            // -------- causal mask --------
            if (jb >= 2 * ib) {
#pragma unroll
                for (int nt = 0; nt < 8; nt++) {
                    int colg = jb * 64 + nt * 8 + 2 * (lane & 3);
                    if (colg     > r0g)     c[nt][0] = -1e30f;
                    if (colg + 1 > r0g)     c[nt][1] = -1e30f;
                    if (colg     > r0g + 8) c[nt][2] = -1e30f;
                    if (colg + 1 > r0g + 8) c[nt][3] = -1e30f;
                }
            }

            // -------- register online softmax --------
            float mx0 = -1e30f, mx1 = -1e30f;
#pragma unroll
            for (int nt = 0; nt < 8; nt++) {
                mx0 = fmaxf(mx0, fmaxf(c[nt][0], c[nt][1]));
                mx1 = fmaxf(mx1, fmaxf(c[nt][2], c[nt][3]));
            }
            mx0 = fmaxf(mx0, __shfl_xor_sync(0xffffffffu, mx0, 1));
            mx0 = fmaxf(mx0, __shfl_xor_sync(0xffffffffu, mx0, 2));
            mx1 = fmaxf(mx1, __shfl_xor_sync(0xffffffffu, mx1, 1));
            mx1 = fmaxf(mx1, __shfl_xor_sync(0xffffffffu, mx1, 2));
            float mn0 = fmaxf(m0, mx0), mn1 = fmaxf(m1, mx1);
            float sc0 = __expf(m0 - mn0), sc1 = __expf(m1 - mn1);
            m0 = mn0; m1 = mn1;
            float s0 = 0.f, s1 = 0.f;
#pragma unroll
            for (int nt = 0; nt < 8; nt++) {
                c[nt][0] = __expf(c[nt][0] - mn0); s0 += c[nt][0];
                c[nt][1] = __expf(c[nt][1] - mn0); s0 += c[nt][1];
                c[nt][2] = __expf(c[nt][2] - mn1); s1 += c[nt][2];
                c[nt][3] = __expf(c[nt][3] - mn1); s1 += c[nt][3];
            }
            s0 += __shfl_xor_sync(0xffffffffu, s0, 1);
            s0 += __shfl_xor_sync(0xffffffffu, s0, 2);
            s1 += __shfl_xor_sync(0xffffffffu, s1, 1);
            s1 += __shfl_xor_sync(0xffffffffu, s1, 2);
            l0 = l0 * sc0 + s0;
            l1 = l1 * sc1 + s1;
#pragma unroll
            for (int nt = 0; nt < 8; nt++) {
                o[nt][0] *= sc0; o[nt][1] *= sc0;
                o[nt][2] *= sc1; o[nt][3] *= sc1;
            }

            // -------- P -> A-fragments --------
            uint32_t ph[4][4], pl[4][4];
#pragma unroll
            for (int kt = 0; kt < 4; kt++) {
                split_pack(c[2 * kt][0],     c[2 * kt][1],     ph[kt][0], pl[kt][0]);
                split_pack(c[2 * kt][2],     c[2 * kt][3],     ph[kt][1], pl[kt][1]);
                split_pack(c[2 * kt + 1][0], c[2 * kt + 1][1], ph[kt][2], pl[kt][2]);
                split_pack(c[2 * kt + 1][2], c[2 * kt + 1][3], ph[kt][3], pl[kt][3]);
            }

            // -------- O += P.V --------
            const int vkey = ((lane >> 3) & 1) * 8 + (lane & 7);
            const int vcol = (lane >> 4) * 8;
#pragma unroll
            for (int ntp = 0; ntp < 4; ntp++) {
#pragma unroll
                for (int kt = 0; kt < 4; kt++) {
                    uint32_t vh[4], vl[4];
                    uint32_t va = stg + (uint32_t)(((kt * 16 + vkey) * LP +
                                                   ntp * 16 + vcol) * 2);
                    ldsm_x4_t(vh, va + ST_VH);
                    ldsm_x4_t(vl, va + ST_VL);
                    mma16816(o[2 * ntp],     ph[kt], vh);
                    mma16816(o[2 * ntp],     ph[kt], vl);
                    mma16816(o[2 * ntp],     pl[kt], vh);
                    mma16816(o[2 * ntp + 1], ph[kt], vh + 2);
                    mma16816(o[2 * ntp + 1], ph[kt], vl + 2);
                    mma16816(o[2 * ntp + 1], pl[kt], vh + 2);
                }
            }
        }
    }

    // -------- normalize + store --------
    {
        float inv0 = 1.0f / l0, inv1 = 1.0f / l1;
        const int cbase = hoff + 2 * (lane & 3);
        float* d0 = outg + (size_t)r0g * DMODEL;
        float* d1 = outg + (size_t)(r0g + 8) * DMODEL;
#pragma unroll
        for (int nt = 0; nt < 8; nt++) {
            float2 v0 = make_float2(o[nt][0] * inv0, o[nt][1] * inv0);
            float2 v1 = make_float2(o[nt][2] * inv1, o[nt][3] * inv1);
            *reinterpret_cast<float2*>(d0 + cbase + nt * 8) = v0;
            *reinterpret_cast<float2*>(d1 + cbase + nt * 8) = v1;
        }
    }
}

// ---------------------------------------------------------------------------
extern "C" void kernel_launch(void* const* d_in, const int* in_sizes, int n_in,
                              void* d_out, int out_size)
{
    const float* x  = (const float*)d_in[0];
    const float* Wq = (const float*)d_in[1];
    const float* Wk = (const float*)d_in[2];
    const float* Wv = (const float*)d_in[3];
    const float* Wo = (const float*)d_in[4];
    const float* bo = (const float*)d_in[5];
    float* out = (float*)d_out;

    float *q, *k, *v, *at;
    __nv_bfloat16 *xh, *xl, *ath, *atl;
    __nv_bfloat16 *qh, *ql, *kh, *kl, *vh, *vl;
    __nv_bfloat16 *wqh, *wql, *wkh, *wkl, *wvh, *wvl, *woh, *wol;
    cudaGetSymbolAddress((void**)&q,  g_q);
    cudaGetSymbolAddress((void**)&k,  g_k);
    cudaGetSymbolAddress((void**)&v,  g_v);
    cudaGetSymbolAddress((void**)&at, g_at);
    cudaGetSymbolAddress((void**)&xh,  g_xh);
    cudaGetSymbolAddress((void**)&xl,  g_xl);
    cudaGetSymbolAddress((void**)&ath, g_ath);
    cudaGetSymbolAddress((void**)&atl, g_atl);
    cudaGetSymbolAddress((void**)&qh, g_qh);
    cudaGetSymbolAddress((void**)&ql, g_ql);
    cudaGetSymbolAddress((void**)&kh, g_kh);
    cudaGetSymbolAddress((void**)&kl, g_kl);
    cudaGetSymbolAddress((void**)&vh, g_vh);
    cudaGetSymbolAddress((void**)&vl, g_vl);
    cudaGetSymbolAddress((void**)&wqh, g_wqh);
    cudaGetSymbolAddress((void**)&wql, g_wql);
    cudaGetSymbolAddress((void**)&wkh, g_wkh);
    cudaGetSymbolAddress((void**)&wkl, g_wkl);
    cudaGetSymbolAddress((void**)&wvh, g_wvh);
    cudaGetSymbolAddress((void**)&wvl, g_wvl);
    cudaGetSymbolAddress((void**)&woh, g_woh);
    cudaGetSymbolAddress((void**)&wol, g_wol);

    cudaFuncSetAttribute(attn_cp,
                         cudaFuncAttributeMaxDynamicSharedMemorySize,
                         ATTN_SMEM);

    const int NSPLIT = SEQ * DMODEL / 1024;

    // prep: split x, transpose+split all weights
    split_kernel<<<NSPLIT, 256>>>(x, xh, xl, 1.0f);
    dim3 gw(DMODEL / 32, DMODEL / 32, 4);
    wsplit_kernel<<<gw, dim3(32, 8)>>>(Wq, Wk, Wv, Wo,
        wqh, wql, wkh, wkl, wvh, wvl, woh, wol);

    // QKV projections (tensor cores) -> fp32
    dim3 g1(DMODEL / 128, SEQ / 128, 3);
    gemm_wmma<<<g1, 256>>>(xh, xl,
        wqh, wql, wkh, wkl, wvh, wvl, q, k, v);

    // pre-split Q (scaled by beta), K, V for attention
    split_kernel<<<NSPLIT, 256>>>(q, qh, ql, 0.125f);
    split_kernel<<<NSPLIT, 256>>>(k, kh, kl, 1.0f);
    split_kernel<<<NSPLIT, 256>>>(v, vh, vl, 1.0f);

    // causal flash attention (cp.async pipelined, register-resident)
    dim3 g2(SEQ / 128, HEADS);
    attn_cp<<<g2, 256, ATTN_SMEM>>>(qh, ql, kh, kl, vh, vl, at);

    // split attention output, then Wo projection
    split_kernel<<<NSPLIT, 256>>>(at, ath, atl, 1.0f);
    dim3 g3(DMODEL / 128, SEQ / 128, 1);
    gemm_wmma<<<g3, 256>>>(ath, atl,
        woh, wol, woh, wol, woh, wol, out, out, out);

    // bias epilogue
    bias_add<<<NSPLIT, 256>>>(out, bo);
}

// round 9
// speedup vs baseline: 1.4235x; 1.4235x over previous
#include <cuda_runtime.h>
#include <cuda_bf16.h>
#include <mma.h>
#include <cstdint>

using namespace nvcuda;

#define SEQ    4096
#define DMODEL 1024
#define HEADS  16
#define DHEAD  64

// ---------------- scratch (no cudaMalloc allowed) ----------------
__device__ float g_q[SEQ * DMODEL];
__device__ float g_k[SEQ * DMODEL];
__device__ float g_v[SEQ * DMODEL];
__device__ float g_at[SEQ * DMODEL];

__device__ __nv_bfloat16 g_xh[SEQ * DMODEL];
__device__ __nv_bfloat16 g_xl[SEQ * DMODEL];
__device__ __nv_bfloat16 g_ath[SEQ * DMODEL];
__device__ __nv_bfloat16 g_atl[SEQ * DMODEL];
__device__ __nv_bfloat16 g_wqh[DMODEL * DMODEL];
__device__ __nv_bfloat16 g_wql[DMODEL * DMODEL];
__device__ __nv_bfloat16 g_wkh[DMODEL * DMODEL];
__device__ __nv_bfloat16 g_wkl[DMODEL * DMODEL];
__device__ __nv_bfloat16 g_wvh[DMODEL * DMODEL];
__device__ __nv_bfloat16 g_wvl[DMODEL * DMODEL];
__device__ __nv_bfloat16 g_woh[DMODEL * DMODEL];
__device__ __nv_bfloat16 g_wol[DMODEL * DMODEL];

__device__ __forceinline__ unsigned pk2(float a, float b) {
    __nv_bfloat162 t = __floats2bfloat162_rn(a, b);
    return *reinterpret_cast<unsigned*>(&t);
}

__device__ __forceinline__ uint32_t smem_u32(const void* p) {
    uint32_t a;
    asm("{ .reg .u64 t; cvta.to.shared.u64 t, %1; cvt.u32.u64 %0, t; }"
        : "=r"(a) : "l"(p));
    return a;
}

// ---------------- prep kernels (unchanged) ----------------
__global__ void __launch_bounds__(256) split_kernel(
    const float* __restrict__ src, __nv_bfloat16* __restrict__ hi,
    __nv_bfloat16* __restrict__ lo)
{
    int i = blockIdx.x * 256 + threadIdx.x;
    float4 v = reinterpret_cast<const float4*>(src)[i];
    __nv_bfloat16 h0 = __float2bfloat16_rn(v.x);
    __nv_bfloat16 h1 = __float2bfloat16_rn(v.y);
    __nv_bfloat16 h2 = __float2bfloat16_rn(v.z);
    __nv_bfloat16 h3 = __float2bfloat16_rn(v.w);
    float r0 = v.x - __bfloat162float(h0);
    float r1 = v.y - __bfloat162float(h1);
    float r2 = v.z - __bfloat162float(h2);
    float r3 = v.w - __bfloat162float(h3);
    uint2 hv, lv;
    __nv_bfloat162 hh0 = {h0, h1}, hh1 = {h2, h3};
    hv.x = *reinterpret_cast<unsigned*>(&hh0);
    hv.y = *reinterpret_cast<unsigned*>(&hh1);
    lv.x = pk2(r0, r1);
    lv.y = pk2(r2, r3);
    reinterpret_cast<uint2*>(hi)[i] = hv;
    reinterpret_cast<uint2*>(lo)[i] = lv;
}

__global__ void __launch_bounds__(256) wsplit_kernel(
    const float* __restrict__ W0, const float* __restrict__ W1,
    const float* __restrict__ W2, const float* __restrict__ W3,
    __nv_bfloat16* H0, __nv_bfloat16* L0, __nv_bfloat16* H1, __nv_bfloat16* L1,
    __nv_bfloat16* H2, __nv_bfloat16* L2, __nv_bfloat16* H3, __nv_bfloat16* L3)
{
    const int z = blockIdx.z;
    const float* W = (z == 0) ? W0 : (z == 1) ? W1 : (z == 2) ? W2 : W3;
    __nv_bfloat16* H = (z == 0) ? H0 : (z == 1) ? H1 : (z == 2) ? H2 : H3;
    __nv_bfloat16* L = (z == 0) ? L0 : (z == 1) ? L1 : (z == 2) ? L2 : L3;

    __shared__ float ts[32][33];
    const int n0 = blockIdx.x * 32, k0 = blockIdx.y * 32;
    const int tx = threadIdx.x, ty = threadIdx.y;
#pragma unroll
    for (int r = 0; r < 4; r++)
        ts[ty + 8 * r][tx] = W[(size_t)(k0 + ty + 8 * r) * DMODEL + n0 + tx];
    __syncthreads();
#pragma unroll
    for (int r = 0; r < 4; r++) {
        int n = n0 + ty + 8 * r;
        float a = ts[tx][ty + 8 * r];
        __nv_bfloat16 h = __float2bfloat16_rn(a);
        H[(size_t)n * DMODEL + k0 + tx] = h;
        L[(size_t)n * DMODEL + k0 + tx] = __float2bfloat16_rn(a - __bfloat162float(h));
    }
}

// ---------------- WMMA split-bf16 GEMM (unchanged from R3) ----------------
#define LDM 40

__global__ void __launch_bounds__(256) gemm_wmma(
    const __nv_bfloat16* __restrict__ Ah, const __nv_bfloat16* __restrict__ Al,
    const __nv_bfloat16* __restrict__ Bh0, const __nv_bfloat16* __restrict__ Bl0,
    const __nv_bfloat16* __restrict__ Bh1, const __nv_bfloat16* __restrict__ Bl1,
    const __nv_bfloat16* __restrict__ Bh2, const __nv_bfloat16* __restrict__ Bl2,
    float* C0, float* C1, float* C2)
{
    const int z = blockIdx.z;
    const __nv_bfloat16* Bh = (z == 0) ? Bh0 : (z == 1) ? Bh1 : Bh2;
    const __nv_bfloat16* Bl = (z == 0) ? Bl0 : (z == 1) ? Bl1 : Bl2;
    float* C = (z == 0) ? C0 : (z == 1) ? C1 : C2;

    __shared__ __nv_bfloat16 As[2][128 * LDM];
    __shared__ __nv_bfloat16 Bs[2][128 * LDM];

    const int tid = threadIdx.x;
    const int wid = tid >> 5;
    const int wm = wid & 3;
    const int wn = wid >> 2;
    const int m0 = blockIdx.y * 128;
    const int n0 = blockIdx.x * 128;

    wmma::fragment<wmma::accumulator, 16, 16, 16, float> acc[2][4];
#pragma unroll
    for (int i = 0; i < 2; i++)
#pragma unroll
        for (int j = 0; j < 4; j++) wmma::fill_fragment(acc[i][j], 0.0f);

    const int r  = tid >> 2;
    const int ch = tid & 3;

    for (int kc = 0; kc < DMODEL; kc += 32) {
#pragma unroll
        for (int hf = 0; hf < 2; hf++) {
            const int row = r + hf * 64;
            const size_t go = (size_t)row * DMODEL + kc + ch * 8;
            const int so = row * LDM + ch * 8;
            *reinterpret_cast<uint4*>(&As[0][so]) =
                *reinterpret_cast<const uint4*>(&Ah[(size_t)m0 * DMODEL + go]);
            *reinterpret_cast<uint4*>(&As[1][so]) =
                *reinterpret_cast<const uint4*>(&Al[(size_t)m0 * DMODEL + go]);
            *reinterpret_cast<uint4*>(&Bs[0][so]) =
                *reinterpret_cast<const uint4*>(&Bh[(size_t)n0 * DMODEL + go]);
            *reinterpret_cast<uint4*>(&Bs[1][so]) =
                *reinterpret_cast<const uint4*>(&Bl[(size_t)n0 * DMODEL + go]);
        }
        __syncthreads();

#pragma unroll
        for (int ks = 0; ks < 32; ks += 16) {
            wmma::fragment<wmma::matrix_a, 16, 16, 16, __nv_bfloat16,
                           wmma::row_major> ah[2], al[2];
#pragma unroll
            for (int i = 0; i < 2; i++) {
                wmma::load_matrix_sync(ah[i], &As[0][(wm * 32 + 16 * i) * LDM + ks], LDM);
                wmma::load_matrix_sync(al[i], &As[1][(wm * 32 + 16 * i) * LDM + ks], LDM);
            }
#pragma unroll
            for (int j = 0; j < 4; j++) {
                wmma::fragment<wmma::matrix_b, 16, 16, 16, __nv_bfloat16,
                               wmma::col_major> bh, bl;
                wmma::load_matrix_sync(bh, &Bs[0][(wn * 64 + 16 * j) * LDM + ks], LDM);
                wmma::load_matrix_sync(bl, &Bs[1][(wn * 64 + 16 * j) * LDM + ks], LDM);
#pragma unroll
                for (int i = 0; i < 2; i++) {
                    wmma::mma_sync(acc[i][j], ah[i], bh, acc[i][j]);
                    wmma::mma_sync(acc[i][j], ah[i], bl, acc[i][j]);
                    wmma::mma_sync(acc[i][j], al[i], bh, acc[i][j]);
                }
            }
        }
        __syncthreads();
    }

#pragma unroll
    for (int i = 0; i < 2; i++)
#pragma unroll
        for (int j = 0; j < 4; j++)
            wmma::store_matrix_sync(
                &C[(size_t)(m0 + wm * 32 + 16 * i) * DMODEL + n0 + wn * 64 + 16 * j],
                acc[i][j], DMODEL, wmma::mem_row_major);
}

__global__ void __launch_bounds__(256) bias_add(
    float* __restrict__ out, const float* __restrict__ bo)
{
    int i = blockIdx.x * 256 + threadIdx.x;
    float4 v = reinterpret_cast<float4*>(out)[i];
    float4 b = *reinterpret_cast<const float4*>(&bo[(i * 4) & (DMODEL - 1)]);
    v.x += b.x; v.y += b.y; v.z += b.z; v.w += b.w;
    reinterpret_cast<float4*>(out)[i] = v;
}

// ---------------- mma.sync flash attention (register-resident, R6) ----------------
// ONE change vs R6: __launch_bounds__(256, 2) -> regs capped at 128 so 2 CTAs
// co-reside per SM (smem 2x36.9KB fits easily), doubling latency hiding.
#define LP 72        // bf16 pitch: rows 144B apart -> ldmatrix conflict-free
#define KOFF_H 0
#define KOFF_L 9216
#define VOFF_H 18432
#define VOFF_L 27648

__device__ __forceinline__ void ldsm_x4(uint32_t* r, uint32_t addr) {
    asm volatile("ldmatrix.sync.aligned.m8n8.x4.shared.b16 {%0,%1,%2,%3}, [%4];"
        : "=r"(r[0]), "=r"(r[1]), "=r"(r[2]), "=r"(r[3]) : "r"(addr));
}
__device__ __forceinline__ void ldsm_x4_t(uint32_t* r, uint32_t addr) {
    asm volatile("ldmatrix.sync.aligned.m8n8.x4.trans.shared.b16 {%0,%1,%2,%3}, [%4];"
        : "=r"(r[0]), "=r"(r[1]), "=r"(r[2]), "=r"(r[3]) : "r"(addr));
}
__device__ __forceinline__ void mma16816(float* c, const uint32_t* a,
                                         const uint32_t* b) {
    asm volatile("mma.sync.aligned.m16n8k16.row.col.f32.bf16.bf16.f32 "
        "{%0,%1,%2,%3}, {%4,%5,%6,%7}, {%8,%9}, {%0,%1,%2,%3};"
        : "+f"(c[0]), "+f"(c[1]), "+f"(c[2]), "+f"(c[3])
        : "r"(a[0]), "r"(a[1]), "r"(a[2]), "r"(a[3]), "r"(b[0]), "r"(b[1]));
}

__device__ __forceinline__ void split_store4(
    __nv_bfloat16* __restrict__ H, __nv_bfloat16* __restrict__ L,
    int idx, float4 v, float scale)
{
    float a0 = v.x * scale, a1 = v.y * scale, a2 = v.z * scale, a3 = v.w * scale;
    __nv_bfloat16 h0 = __float2bfloat16_rn(a0);
    __nv_bfloat16 h1 = __float2bfloat16_rn(a1);
    __nv_bfloat16 h2 = __float2bfloat16_rn(a2);
    __nv_bfloat16 h3 = __float2bfloat16_rn(a3);
    uint2 hw, lw;
    __nv_bfloat162 p0 = {h0, h1}, p1 = {h2, h3};
    hw.x = *reinterpret_cast<unsigned*>(&p0);
    hw.y = *reinterpret_cast<unsigned*>(&p1);
    lw.x = pk2(a0 - __bfloat162float(h0), a1 - __bfloat162float(h1));
    lw.y = pk2(a2 - __bfloat162float(h2), a3 - __bfloat162float(h3));
    *reinterpret_cast<uint2*>(H + idx) = hw;
    *reinterpret_cast<uint2*>(L + idx) = lw;
}

__device__ __forceinline__ void split_pack(float a, float b,
                                           uint32_t& h, uint32_t& l)
{
    __nv_bfloat16 ha = __float2bfloat16_rn(a);
    __nv_bfloat16 hb = __float2bfloat16_rn(b);
    __nv_bfloat162 hh = {ha, hb};
    h = *reinterpret_cast<unsigned*>(&hh);
    l = pk2(a - __bfloat162float(ha), b - __bfloat162float(hb));
}

__global__ void __launch_bounds__(256, 2) attn_mma(
    const float* __restrict__ qg, const float* __restrict__ kg,
    const float* __restrict__ vg, float* __restrict__ outg)
{
    __shared__ char smc[36864];
    __nv_bfloat16* Kh = reinterpret_cast<__nv_bfloat16*>(smc + KOFF_H);
    __nv_bfloat16* Kl = reinterpret_cast<__nv_bfloat16*>(smc + KOFF_L);
    __nv_bfloat16* Vh = reinterpret_cast<__nv_bfloat16*>(smc + VOFF_H);
    __nv_bfloat16* Vl = reinterpret_cast<__nv_bfloat16*>(smc + VOFF_L);

    const int tid  = threadIdx.x;
    const int w    = tid >> 5;
    const int lane = tid & 31;
    const int h    = blockIdx.y;
    const int ib   = (int)(gridDim.x - 1u - blockIdx.x);  // heavy first
    const int row0 = ib * 128;
    const int hoff = h * DHEAD;
    const uint32_t smb = smem_u32(smc);

    // -------- stage Q (128x64, beta-scaled, hi/lo) through K/V region --------
    {
        __nv_bfloat16* Qh = reinterpret_cast<__nv_bfloat16*>(smc);
        __nv_bfloat16* Ql = reinterpret_cast<__nv_bfloat16*>(smc + 18432);
        const int r  = tid >> 1;
        const int cb = (tid & 1) * 32;
        const float* qp = qg + (size_t)(row0 + r) * DMODEL + hoff + cb;
#pragma unroll
        for (int u = 0; u < 8; u++) {
            float4 v = *reinterpret_cast<const float4*>(qp + 4 * u);
            split_store4(Qh, Ql, r * LP + cb + 4 * u, v, 0.125f);
        }
    }
    __syncthreads();

    // -------- persistent Q A-fragments (16 rows per warp, K=64) --------
    uint32_t qh[4][4], ql[4][4];
    {
        const int qrow = w * 16 + (lane & 15);
        const int csel = (lane >> 4) * 8;
#pragma unroll
        for (int kt = 0; kt < 4; kt++) {
            uint32_t ah = smb + (uint32_t)((qrow * LP + kt * 16 + csel) * 2);
            ldsm_x4(qh[kt], ah);
            ldsm_x4(ql[kt], ah + 18432);
        }
    }
    __syncthreads();

    float o[8][4];
#pragma unroll
    for (int nt = 0; nt < 8; nt++)
#pragma unroll
        for (int j = 0; j < 4; j++) o[nt][j] = 0.f;
    float m0 = -1e30f, m1 = -1e30f, l0 = 0.f, l1 = 0.f;

    const int r0g = row0 + w * 16 + (lane >> 2);  // this thread's first row
    const int jmax = 2 * ib + 1;

    for (int jb = 0; jb <= jmax; jb++) {
        // -------- load K/V tile (64x64), hi/lo split --------
        {
            const int r  = tid >> 2;
            const int cb = (tid & 3) * 16;
            const float* kp = kg + (size_t)(jb * 64 + r) * DMODEL + hoff + cb;
            const float* vp = vg + (size_t)(jb * 64 + r) * DMODEL + hoff + cb;
#pragma unroll
            for (int u = 0; u < 4; u++) {
                float4 kv = *reinterpret_cast<const float4*>(kp + 4 * u);
                float4 vv = *reinterpret_cast<const float4*>(vp + 4 * u);
                split_store4(Kh, Kl, r * LP + cb + 4 * u, kv, 1.0f);
                split_store4(Vh, Vl, r * LP + cb + 4 * u, vv, 1.0f);
            }
        }
        __syncthreads();

        // warp entirely in the future of this key tile? (warp-uniform)
        if (jb * 64 <= row0 + w * 16 + 15) {
            // -------- S = Q.K^T : 16x64 in registers --------
            float c[8][4];
#pragma unroll
            for (int nt = 0; nt < 8; nt++)
#pragma unroll
                for (int j = 0; j < 4; j++) c[nt][j] = 0.f;

            const int kkey = (lane >> 4) * 8 + (lane & 7);
            const int kcol = ((lane >> 3) & 1) * 8;
#pragma unroll
            for (int kt = 0; kt < 4; kt++) {
#pragma unroll
                for (int ntp = 0; ntp < 4; ntp++) {
                    uint32_t bh[4], bl[4];
                    uint32_t ka = smb + (uint32_t)(((ntp * 16 + kkey) * LP +
                                                   kt * 16 + kcol) * 2);
                    ldsm_x4(bh, ka + KOFF_H);
                    ldsm_x4(bl, ka + KOFF_L);
                    mma16816(c[2 * ntp],     qh[kt], bh);
                    mma16816(c[2 * ntp],     qh[kt], bl);
                    mma16816(c[2 * ntp],     ql[kt], bh);
                    mma16816(c[2 * ntp + 1], qh[kt], bh + 2);
                    mma16816(c[2 * ntp + 1], qh[kt], bl + 2);
                    mma16816(c[2 * ntp + 1], ql[kt], bh + 2);
                }
            }

            // -------- causal mask (only near/on diagonal) --------
            if (jb >= 2 * ib) {
#pragma unroll
                for (int nt = 0; nt < 8; nt++) {
                    int colg = jb * 64 + nt * 8 + 2 * (lane & 3);
                    if (colg     > r0g)     c[nt][0] = -1e30f;
                    if (colg + 1 > r0g)     c[nt][1] = -1e30f;
                    if (colg     > r0g + 8) c[nt][2] = -1e30f;
                    if (colg + 1 > r0g + 8) c[nt][3] = -1e30f;
                }
            }

            // -------- register online softmax (rows r0g, r0g+8) --------
            float mx0 = -1e30f, mx1 = -1e30f;
#pragma unroll
            for (int nt = 0; nt < 8; nt++) {
                mx0 = fmaxf(mx0, fmaxf(c[nt][0], c[nt][1]));
                mx1 = fmaxf(mx1, fmaxf(c[nt][2], c[nt][3]));
            }
            mx0 = fmaxf(mx0, __shfl_xor_sync(0xffffffffu, mx0, 1));
            mx0 = fmaxf(mx0, __shfl_xor_sync(0xffffffffu, mx0, 2));
            mx1 = fmaxf(mx1, __shfl_xor_sync(0xffffffffu, mx1, 1));
            mx1 = fmaxf(mx1, __shfl_xor_sync(0xffffffffu, mx1, 2));
            float mn0 = fmaxf(m0, mx0), mn1 = fmaxf(m1, mx1);
            float sc0 = __expf(m0 - mn0), sc1 = __expf(m1 - mn1);
            m0 = mn0; m1 = mn1;
            float s0 = 0.f, s1 = 0.f;
#pragma unroll
            for (int nt = 0; nt < 8; nt++) {
                c[nt][0] = __expf(c[nt][0] - mn0); s0 += c[nt][0];
                c[nt][1] = __expf(c[nt][1] - mn0); s0 += c[nt][1];
                c[nt][2] = __expf(c[nt][2] - mn1); s1 += c[nt][2];
                c[nt][3] = __expf(c[nt][3] - mn1); s1 += c[nt][3];
            }
            s0 += __shfl_xor_sync(0xffffffffu, s0, 1);
            s0 += __shfl_xor_sync(0xffffffffu, s0, 2);
            s1 += __shfl_xor_sync(0xffffffffu, s1, 1);
            s1 += __shfl_xor_sync(0xffffffffu, s1, 2);
            l0 = l0 * sc0 + s0;
            l1 = l1 * sc1 + s1;
#pragma unroll
            for (int nt = 0; nt < 8; nt++) {
                o[nt][0] *= sc0; o[nt][1] *= sc0;
                o[nt][2] *= sc1; o[nt][3] *= sc1;
            }

            // -------- P -> A-fragments (register reuse, hi/lo) --------
            uint32_t ph[4][4], pl[4][4];
#pragma unroll
            for (int kt = 0; kt < 4; kt++) {
                split_pack(c[2 * kt][0],     c[2 * kt][1],     ph[kt][0], pl[kt][0]);
                split_pack(c[2 * kt][2],     c[2 * kt][3],     ph[kt][1], pl[kt][1]);
                split_pack(c[2 * kt + 1][0], c[2 * kt + 1][1], ph[kt][2], pl[kt][2]);
                split_pack(c[2 * kt + 1][2], c[2 * kt + 1][3], ph[kt][3], pl[kt][3]);
            }

            // -------- O += P.V --------
            const int vkey = ((lane >> 3) & 1) * 8 + (lane & 7);
            const int vcol = (lane >> 4) * 8;
#pragma unroll
            for (int ntp = 0; ntp < 4; ntp++) {
#pragma unroll
                for (int kt = 0; kt < 4; kt++) {
                    uint32_t vh[4], vl[4];
                    uint32_t va = smb + (uint32_t)(((kt * 16 + vkey) * LP +
                                                   ntp * 16 + vcol) * 2);
                    ldsm_x4_t(vh, va + VOFF_H);
                    ldsm_x4_t(vl, va + VOFF_L);
                    mma16816(o[2 * ntp],     ph[kt], vh);
                    mma16816(o[2 * ntp],     ph[kt], vl);
                    mma16816(o[2 * ntp],     pl[kt], vh);
                    mma16816(o[2 * ntp + 1], ph[kt], vh + 2);
                    mma16816(o[2 * ntp + 1], ph[kt], vl + 2);
                    mma16816(o[2 * ntp + 1], pl[kt], vh + 2);
                }
            }
        }
        __syncthreads();
    }

    // -------- normalize + store --------
    {
        float inv0 = 1.0f / l0, inv1 = 1.0f / l1;
        const int cbase = hoff + 2 * (lane & 3);
        float* d0 = outg + (size_t)r0g * DMODEL;
        float* d1 = outg + (size_t)(r0g + 8) * DMODEL;
#pragma unroll
        for (int nt = 0; nt < 8; nt++) {
            float2 v0 = make_float2(o[nt][0] * inv0, o[nt][1] * inv0);
            float2 v1 = make_float2(o[nt][2] * inv1, o[nt][3] * inv1);
            *reinterpret_cast<float2*>(d0 + cbase + nt * 8) = v0;
            *reinterpret_cast<float2*>(d1 + cbase + nt * 8) = v1;
        }
    }
}

// ---------------------------------------------------------------------------
extern "C" void kernel_launch(void* const* d_in, const int* in_sizes, int n_in,
                              void* d_out, int out_size)
{
    const float* x  = (const float*)d_in[0];
    const float* Wq = (const float*)d_in[1];
    const float* Wk = (const float*)d_in[2];
    const float* Wv = (const float*)d_in[3];
    const float* Wo = (const float*)d_in[4];
    const float* bo = (const float*)d_in[5];
    float* out = (float*)d_out;

    float *q, *k, *v, *at;
    __nv_bfloat16 *xh, *xl, *ath, *atl;
    __nv_bfloat16 *wqh, *wql, *wkh, *wkl, *wvh, *wvl, *woh, *wol;
    cudaGetSymbolAddress((void**)&q,  g_q);
    cudaGetSymbolAddress((void**)&k,  g_k);
    cudaGetSymbolAddress((void**)&v,  g_v);
    cudaGetSymbolAddress((void**)&at, g_at);
    cudaGetSymbolAddress((void**)&xh,  g_xh);
    cudaGetSymbolAddress((void**)&xl,  g_xl);
    cudaGetSymbolAddress((void**)&ath, g_ath);
    cudaGetSymbolAddress((void**)&atl, g_atl);
    cudaGetSymbolAddress((void**)&wqh, g_wqh);
    cudaGetSymbolAddress((void**)&wql, g_wql);
    cudaGetSymbolAddress((void**)&wkh, g_wkh);
    cudaGetSymbolAddress((void**)&wkl, g_wkl);
    cudaGetSymbolAddress((void**)&wvh, g_wvh);
    cudaGetSymbolAddress((void**)&wvl, g_wvl);
    cudaGetSymbolAddress((void**)&woh, g_woh);
    cudaGetSymbolAddress((void**)&wol, g_wol);

    // prep: split x, transpose+split all weights
    split_kernel<<<SEQ * DMODEL / 1024, 256>>>(x, xh, xl);
    dim3 gw(DMODEL / 32, DMODEL / 32, 4);
    wsplit_kernel<<<gw, dim3(32, 8)>>>(Wq, Wk, Wv, Wo,
        wqh, wql, wkh, wkl, wvh, wvl, woh, wol);

    // QKV projections (tensor cores)
    dim3 g1(DMODEL / 128, SEQ / 128, 3);
    gemm_wmma<<<g1, 256>>>(xh, xl,
        wqh, wql, wkh, wkl, wvh, wvl, q, k, v);

    // causal flash attention (mma.sync, register-resident, 2 CTAs/SM)
    dim3 g2(SEQ / 128, HEADS);
    attn_mma<<<g2, 256>>>(q, k, v, at);

    // split attention output, then Wo projection
    split_kernel<<<SEQ * DMODEL / 1024, 256>>>(at, ath, atl);
    dim3 g3(DMODEL / 128, SEQ / 128, 1);
    gemm_wmma<<<g3, 256>>>(ath, atl,
        woh, wol, woh, wol, woh, wol, out, out, out);

    // bias epilogue
    bias_add<<<SEQ * DMODEL / 1024, 256>>>(out, bo);
}

// round 13
// speedup vs baseline: 1.6591x; 1.1655x over previous
#include <cuda_runtime.h>
#include <cuda_bf16.h>
#include <mma.h>
#include <cstdint>

using namespace nvcuda;

#define SEQ    4096
#define DMODEL 1024
#define HEADS  16
#define DHEAD  64

// ---------------- scratch (no cudaMalloc allowed) ----------------
__device__ float g_q[SEQ * DMODEL];
__device__ float g_k[SEQ * DMODEL];
__device__ float g_v[SEQ * DMODEL];
__device__ float g_at[SEQ * DMODEL];

__device__ __nv_bfloat16 g_xh[SEQ * DMODEL];
__device__ __nv_bfloat16 g_xl[SEQ * DMODEL];
__device__ __nv_bfloat16 g_ath[SEQ * DMODEL];
__device__ __nv_bfloat16 g_atl[SEQ * DMODEL];
__device__ __nv_bfloat16 g_qh[SEQ * DMODEL];
__device__ __nv_bfloat16 g_ql[SEQ * DMODEL];
__device__ __nv_bfloat16 g_kh[SEQ * DMODEL];
__device__ __nv_bfloat16 g_kl[SEQ * DMODEL];
__device__ __nv_bfloat16 g_vh[SEQ * DMODEL];
__device__ __nv_bfloat16 g_vl[SEQ * DMODEL];
__device__ __nv_bfloat16 g_wqh[DMODEL * DMODEL];
__device__ __nv_bfloat16 g_wql[DMODEL * DMODEL];
__device__ __nv_bfloat16 g_wkh[DMODEL * DMODEL];
__device__ __nv_bfloat16 g_wkl[DMODEL * DMODEL];
__device__ __nv_bfloat16 g_wvh[DMODEL * DMODEL];
__device__ __nv_bfloat16 g_wvl[DMODEL * DMODEL];
__device__ __nv_bfloat16 g_woh[DMODEL * DMODEL];
__device__ __nv_bfloat16 g_wol[DMODEL * DMODEL];

__device__ __forceinline__ unsigned pk2(float a, float b) {
    __nv_bfloat162 t = __floats2bfloat162_rn(a, b);
    return *reinterpret_cast<unsigned*>(&t);
}

__device__ __forceinline__ uint32_t smem_u32(const void* p) {
    uint32_t a;
    asm("{ .reg .u64 t; cvta.to.shared.u64 t, %1; cvt.u32.u64 %0, t; }"
        : "=r"(a) : "l"(p));
    return a;
}

// ---------------- prep kernels ----------------
__global__ void __launch_bounds__(256) split_kernel(
    const float* __restrict__ src, __nv_bfloat16* __restrict__ hi,
    __nv_bfloat16* __restrict__ lo, float scale)
{
    int i = blockIdx.x * 256 + threadIdx.x;
    float4 v = reinterpret_cast<const float4*>(src)[i];
    v.x *= scale; v.y *= scale; v.z *= scale; v.w *= scale;
    __nv_bfloat16 h0 = __float2bfloat16_rn(v.x);
    __nv_bfloat16 h1 = __float2bfloat16_rn(v.y);
    __nv_bfloat16 h2 = __float2bfloat16_rn(v.z);
    __nv_bfloat16 h3 = __float2bfloat16_rn(v.w);
    float r0 = v.x - __bfloat162float(h0);
    float r1 = v.y - __bfloat162float(h1);
    float r2 = v.z - __bfloat162float(h2);
    float r3 = v.w - __bfloat162float(h3);
    uint2 hv, lv;
    __nv_bfloat162 hh0 = {h0, h1}, hh1 = {h2, h3};
    hv.x = *reinterpret_cast<unsigned*>(&hh0);
    hv.y = *reinterpret_cast<unsigned*>(&hh1);
    lv.x = pk2(r0, r1);
    lv.y = pk2(r2, r3);
    reinterpret_cast<uint2*>(hi)[i] = hv;
    reinterpret_cast<uint2*>(lo)[i] = lv;
}

__global__ void __launch_bounds__(256) wsplit_kernel(
    const float* __restrict__ W0, const float* __restrict__ W1,
    const float* __restrict__ W2, const float* __restrict__ W3,
    __nv_bfloat16* H0, __nv_bfloat16* L0, __nv_bfloat16* H1, __nv_bfloat16* L1,
    __nv_bfloat16* H2, __nv_bfloat16* L2, __nv_bfloat16* H3, __nv_bfloat16* L3)
{
    const int z = blockIdx.z;
    const float* W = (z == 0) ? W0 : (z == 1) ? W1 : (z == 2) ? W2 : W3;
    __nv_bfloat16* H = (z == 0) ? H0 : (z == 1) ? H1 : (z == 2) ? H2 : H3;
    __nv_bfloat16* L = (z == 0) ? L0 : (z == 1) ? L1 : (z == 2) ? L2 : L3;

    __shared__ float ts[32][33];
    const int n0 = blockIdx.x * 32, k0 = blockIdx.y * 32;
    const int tx = threadIdx.x, ty = threadIdx.y;
#pragma unroll
    for (int r = 0; r < 4; r++)
        ts[ty + 8 * r][tx] = W[(size_t)(k0 + ty + 8 * r) * DMODEL + n0 + tx];
    __syncthreads();
#pragma unroll
    for (int r = 0; r < 4; r++) {
        int n = n0 + ty + 8 * r;
        float a = ts[tx][ty + 8 * r];
        __nv_bfloat16 h = __float2bfloat16_rn(a);
        H[(size_t)n * DMODEL + k0 + tx] = h;
        L[(size_t)n * DMODEL + k0 + tx] = __float2bfloat16_rn(a - __bfloat162float(h));
    }
}

// ---------------- WMMA split-bf16 GEMM, double-buffered ----------------
// Dynamic smem: 2 stages x (AH, AL, BH, BL), each 128x32 bf16, pitch LDM=40.
#define LDM 40
#define GS_ELEMS  (128 * LDM)            // 5120 bf16 per sub-tile
#define GS_STAGE  (4 * GS_ELEMS)         // 20480 bf16 per stage
#define GEMM_SMEM (2 * GS_STAGE * 2)     // 81920 bytes

__global__ void __launch_bounds__(256) gemm_wmma(
    const __nv_bfloat16* __restrict__ Ah, const __nv_bfloat16* __restrict__ Al,
    const __nv_bfloat16* __restrict__ Bh0, const __nv_bfloat16* __restrict__ Bl0,
    const __nv_bfloat16* __restrict__ Bh1, const __nv_bfloat16* __restrict__ Bl1,
    const __nv_bfloat16* __restrict__ Bh2, const __nv_bfloat16* __restrict__ Bl2,
    float* C0, float* C1, float* C2)
{
    const int z = blockIdx.z;
    const __nv_bfloat16* Bh = (z == 0) ? Bh0 : (z == 1) ? Bh1 : Bh2;
    const __nv_bfloat16* Bl = (z == 0) ? Bl0 : (z == 1) ? Bl1 : Bl2;
    float* C = (z == 0) ? C0 : (z == 1) ? C1 : C2;

    extern __shared__ __nv_bfloat16 gsm[];

    const int tid = threadIdx.x;
    const int wid = tid >> 5;
    const int wm = wid & 3;
    const int wn = wid >> 2;
    const int m0 = blockIdx.y * 128;
    const int n0 = blockIdx.x * 128;

    wmma::fragment<wmma::accumulator, 16, 16, 16, float> acc[2][4];
#pragma unroll
    for (int i = 0; i < 2; i++)
#pragma unroll
        for (int j = 0; j < 4; j++) wmma::fill_fragment(acc[i][j], 0.0f);

    const int r  = tid >> 2;           // 0..63
    const int ch = tid & 3;            // 8-elem chunk within 32

    const __nv_bfloat16* gA[2] = {Ah + (size_t)m0 * DMODEL,
                                  Al + (size_t)m0 * DMODEL};
    const __nv_bfloat16* gB[2] = {Bh + (size_t)n0 * DMODEL,
                                  Bl + (size_t)n0 * DMODEL};

    uint4 rg[8];   // staged loads: [hf][AH,AL,BH,BL]

    // ---- prologue: load + store tile 0 ----
#pragma unroll
    for (int hf = 0; hf < 2; hf++) {
        const int row = r + hf * 64;
        const size_t go = (size_t)row * DMODEL + ch * 8;
        rg[hf * 4 + 0] = *reinterpret_cast<const uint4*>(gA[0] + go);
        rg[hf * 4 + 1] = *reinterpret_cast<const uint4*>(gA[1] + go);
        rg[hf * 4 + 2] = *reinterpret_cast<const uint4*>(gB[0] + go);
        rg[hf * 4 + 3] = *reinterpret_cast<const uint4*>(gB[1] + go);
    }
#pragma unroll
    for (int hf = 0; hf < 2; hf++) {
        const int so = (r + hf * 64) * LDM + ch * 8;
        *reinterpret_cast<uint4*>(&gsm[0 * GS_ELEMS + so]) = rg[hf * 4 + 0];
        *reinterpret_cast<uint4*>(&gsm[1 * GS_ELEMS + so]) = rg[hf * 4 + 1];
        *reinterpret_cast<uint4*>(&gsm[2 * GS_ELEMS + so]) = rg[hf * 4 + 2];
        *reinterpret_cast<uint4*>(&gsm[3 * GS_ELEMS + so]) = rg[hf * 4 + 3];
    }
    __syncthreads();

    for (int it = 0; it < 32; it++) {
        const bool has_next = (it < 31);
        // issue next tile's loads early (hide LDG latency under compute)
        if (has_next) {
            const int kc = (it + 1) * 32;
#pragma unroll
            for (int hf = 0; hf < 2; hf++) {
                const int row = r + hf * 64;
                const size_t go = (size_t)row * DMODEL + kc + ch * 8;
                rg[hf * 4 + 0] = *reinterpret_cast<const uint4*>(gA[0] + go);
                rg[hf * 4 + 1] = *reinterpret_cast<const uint4*>(gA[1] + go);
                rg[hf * 4 + 2] = *reinterpret_cast<const uint4*>(gB[0] + go);
                rg[hf * 4 + 3] = *reinterpret_cast<const uint4*>(gB[1] + go);
            }
        }

        // compute current stage
        __nv_bfloat16* As0 = gsm + (it & 1) * GS_STAGE;
        __nv_bfloat16* As1 = As0 + GS_ELEMS;
        __nv_bfloat16* Bs0 = As0 + 2 * GS_ELEMS;
        __nv_bfloat16* Bs1 = As0 + 3 * GS_ELEMS;
#pragma unroll
        for (int ks = 0; ks < 32; ks += 16) {
            wmma::fragment<wmma::matrix_a, 16, 16, 16, __nv_bfloat16,
                           wmma::row_major> ah[2], al[2];
#pragma unroll
            for (int i = 0; i < 2; i++) {
                wmma::load_matrix_sync(ah[i], &As0[(wm * 32 + 16 * i) * LDM + ks], LDM);
                wmma::load_matrix_sync(al[i], &As1[(wm * 32 + 16 * i) * LDM + ks], LDM);
            }
#pragma unroll
            for (int j = 0; j < 4; j++) {
                wmma::fragment<wmma::matrix_b, 16, 16, 16, __nv_bfloat16,
                               wmma::col_major> bh, bl;
                wmma::load_matrix_sync(bh, &Bs0[(wn * 64 + 16 * j) * LDM + ks], LDM);
                wmma::load_matrix_sync(bl, &Bs1[(wn * 64 + 16 * j) * LDM + ks], LDM);
#pragma unroll
                for (int i = 0; i < 2; i++) {
                    wmma::mma_sync(acc[i][j], ah[i], bh, acc[i][j]);
                    wmma::mma_sync(acc[i][j], ah[i], bl, acc[i][j]);
                    wmma::mma_sync(acc[i][j], al[i], bh, acc[i][j]);
                }
            }
        }

        // store next tile into the other stage
        if (has_next) {
            __nv_bfloat16* ns = gsm + ((it + 1) & 1) * GS_STAGE;
#pragma unroll
            for (int hf = 0; hf < 2; hf++) {
                const int so = (r + hf * 64) * LDM + ch * 8;
                *reinterpret_cast<uint4*>(&ns[0 * GS_ELEMS + so]) = rg[hf * 4 + 0];
                *reinterpret_cast<uint4*>(&ns[1 * GS_ELEMS + so]) = rg[hf * 4 + 1];
                *reinterpret_cast<uint4*>(&ns[2 * GS_ELEMS + so]) = rg[hf * 4 + 2];
                *reinterpret_cast<uint4*>(&ns[3 * GS_ELEMS + so]) = rg[hf * 4 + 3];
            }
        }
        __syncthreads();
    }

#pragma unroll
    for (int i = 0; i < 2; i++)
#pragma unroll
        for (int j = 0; j < 4; j++)
            wmma::store_matrix_sync(
                &C[(size_t)(m0 + wm * 32 + 16 * i) * DMODEL + n0 + wn * 64 + 16 * j],
                acc[i][j], DMODEL, wmma::mem_row_major);
}

__global__ void __launch_bounds__(256) bias_add(
    float* __restrict__ out, const float* __restrict__ bo)
{
    int i = blockIdx.x * 256 + threadIdx.x;
    float4 v = reinterpret_cast<float4*>(out)[i];
    float4 b = *reinterpret_cast<const float4*>(&bo[(i * 4) & (DMODEL - 1)]);
    v.x += b.x; v.y += b.y; v.z += b.z; v.w += b.w;
    reinterpret_cast<float4*>(out)[i] = v;
}

// ---------------- mma.sync flash attention (pre-split bf16 inputs) ----------------
// R8 structure exactly; only the loaders changed: Q/K/V arrive pre-split hi/lo
// bf16, so the in-kernel path is pure LDG.128 -> STS.128 (no conversion math).
#define LP 72        // bf16 pitch: rows 144B apart -> ldmatrix conflict-free
#define KOFF_H 0
#define KOFF_L 9216
#define VOFF_H 18432
#define VOFF_L 27648

__device__ __forceinline__ void ldsm_x4(uint32_t* r, uint32_t addr) {
    asm volatile("ldmatrix.sync.aligned.m8n8.x4.shared.b16 {%0,%1,%2,%3}, [%4];"
        : "=r"(r[0]), "=r"(r[1]), "=r"(r[2]), "=r"(r[3]) : "r"(addr));
}
__device__ __forceinline__ void ldsm_x4_t(uint32_t* r, uint32_t addr) {
    asm volatile("ldmatrix.sync.aligned.m8n8.x4.trans.shared.b16 {%0,%1,%2,%3}, [%4];"
        : "=r"(r[0]), "=r"(r[1]), "=r"(r[2]), "=r"(r[3]) : "r"(addr));
}
__device__ __forceinline__ void mma16816(float* c, const uint32_t* a,
                                         const uint32_t* b) {
    asm volatile("mma.sync.aligned.m16n8k16.row.col.f32.bf16.bf16.f32 "
        "{%0,%1,%2,%3}, {%4,%5,%6,%7}, {%8,%9}, {%0,%1,%2,%3};"
        : "+f"(c[0]), "+f"(c[1]), "+f"(c[2]), "+f"(c[3])
        : "r"(a[0]), "r"(a[1]), "r"(a[2]), "r"(a[3]), "r"(b[0]), "r"(b[1]));
}

__device__ __forceinline__ void split_pack(float a, float b,
                                           uint32_t& h, uint32_t& l)
{
    __nv_bfloat16 ha = __float2bfloat16_rn(a);
    __nv_bfloat16 hb = __float2bfloat16_rn(b);
    __nv_bfloat162 hh = {ha, hb};
    h = *reinterpret_cast<unsigned*>(&hh);
    l = pk2(a - __bfloat162float(ha), b - __bfloat162float(hb));
}

__global__ void __launch_bounds__(256, 2) attn_mma(
    const __nv_bfloat16* __restrict__ qh_g, const __nv_bfloat16* __restrict__ ql_g,
    const __nv_bfloat16* __restrict__ kh_g, const __nv_bfloat16* __restrict__ kl_g,
    const __nv_bfloat16* __restrict__ vh_g, const __nv_bfloat16* __restrict__ vl_g,
    float* __restrict__ outg)
{
    __shared__ char smc[36864];

    const int tid  = threadIdx.x;
    const int w    = tid >> 5;
    const int lane = tid & 31;
    const int h    = blockIdx.y;
    const int ib   = (int)(gridDim.x - 1u - blockIdx.x);  // heavy first
    const int row0 = ib * 128;
    const int hoff = h * DHEAD;
    const uint32_t smb = smem_u32(smc);

    // -------- stage Q (pre-scaled, pre-split) through K/V region --------
    {
#pragma unroll
        for (int u = 0; u < 4; u++) {
            const int unit = tid + 256 * u;          // 0..1023
            const int r = unit >> 3, ch = unit & 7;
            const size_t go = (size_t)(row0 + r) * DMODEL + hoff + ch * 8;
            *reinterpret_cast<uint4*>(smc + r * 144 + ch * 16) =
                *reinterpret_cast<const uint4*>(qh_g + go);
            *reinterpret_cast<uint4*>(smc + 18432 + r * 144 + ch * 16) =
                *reinterpret_cast<const uint4*>(ql_g + go);
        }
    }
    __syncthreads();

    // -------- persistent Q A-fragments (16 rows per warp, K=64) --------
    uint32_t qh[4][4], ql[4][4];
    {
        const int qrow = w * 16 + (lane & 15);
        const int csel = (lane >> 4) * 8;
#pragma unroll
        for (int kt = 0; kt < 4; kt++) {
            uint32_t ah = smb + (uint32_t)((qrow * LP + kt * 16 + csel) * 2);
            ldsm_x4(qh[kt], ah);
            ldsm_x4(ql[kt], ah + 18432);
        }
    }
    __syncthreads();

    float o[8][4];
#pragma unroll
    for (int nt = 0; nt < 8; nt++)
#pragma unroll
        for (int j = 0; j < 4; j++) o[nt][j] = 0.f;
    float m0 = -1e30f, m1 = -1e30f, l0 = 0.f, l1 = 0.f;

    const int r0g = row0 + w * 16 + (lane >> 2);  // this thread's first row
    const int jmax = 2 * ib + 1;

    for (int jb = 0; jb <= jmax; jb++) {
        // -------- load K/V tile (pre-split): pure LDG.128 -> STS.128 --------
        {
#pragma unroll
            for (int u = 0; u < 2; u++) {
                const int unit = tid + 256 * u;      // 0..511
                const int r = unit >> 3, ch = unit & 7;
                const size_t go = (size_t)(jb * 64 + r) * DMODEL + hoff + ch * 8;
                const int so = r * 144 + ch * 16;
                *reinterpret_cast<uint4*>(smc + KOFF_H + so) =
                    *reinterpret_cast<const uint4*>(kh_g + go);
                *reinterpret_cast<uint4*>(smc + KOFF_L + so) =
                    *reinterpret_cast<const uint4*>(kl_g + go);
                *reinterpret_cast<uint4*>(smc + VOFF_H + so) =
                    *reinterpret_cast<const uint4*>(vh_g + go);
                *reinterpret_cast<uint4*>(smc + VOFF_L + so) =
                    *reinterpret_cast<const uint4*>(vl_g + go);
            }
        }
        __syncthreads();

        // warp entirely in the future of this key tile? (warp-uniform)
        if (jb * 64 <= row0 + w * 16 + 15) {
            // -------- S = Q.K^T : 16x64 in registers --------
            float c[8][4];
#pragma unroll
            for (int nt = 0; nt < 8; nt++)
#pragma unroll
                for (int j = 0; j < 4; j++) c[nt][j] = 0.f;

            const int kkey = (lane >> 4) * 8 + (lane & 7);
            const int kcol = ((lane >> 3) & 1) * 8;
#pragma unroll
            for (int kt = 0; kt < 4; kt++) {
#pragma unroll
                for (int ntp = 0; ntp < 4; ntp++) {
                    uint32_t bh[4], bl[4];
                    uint32_t ka = smb + (uint32_t)(((ntp * 16 + kkey) * LP +
                                                   kt * 16 + kcol) * 2);
                    ldsm_x4(bh, ka + KOFF_H);
                    ldsm_x4(bl, ka + KOFF_L);
                    mma16816(c[2 * ntp],     qh[kt], bh);
                    mma16816(c[2 * ntp],     qh[kt], bl);
                    mma16816(c[2 * ntp],     ql[kt], bh);
                    mma16816(c[2 * ntp + 1], qh[kt], bh + 2);
                    mma16816(c[2 * ntp + 1], qh[kt], bl + 2);
                    mma16816(c[2 * ntp + 1], ql[kt], bh + 2);
                }
            }

            // -------- causal mask (only near/on diagonal) --------
            if (jb >= 2 * ib) {
#pragma unroll
                for (int nt = 0; nt < 8; nt++) {
                    int colg = jb * 64 + nt * 8 + 2 * (lane & 3);
                    if (colg     > r0g)     c[nt][0] = -1e30f;
                    if (colg + 1 > r0g)     c[nt][1] = -1e30f;
                    if (colg     > r0g + 8) c[nt][2] = -1e30f;
                    if (colg + 1 > r0g + 8) c[nt][3] = -1e30f;
                }
            }

            // -------- register online softmax (rows r0g, r0g+8) --------
            float mx0 = -1e30f, mx1 = -1e30f;
#pragma unroll
            for (int nt = 0; nt < 8; nt++) {
                mx0 = fmaxf(mx0, fmaxf(c[nt][0], c[nt][1]));
                mx1 = fmaxf(mx1, fmaxf(c[nt][2], c[nt][3]));
            }
            mx0 = fmaxf(mx0, __shfl_xor_sync(0xffffffffu, mx0, 1));
            mx0 = fmaxf(mx0, __shfl_xor_sync(0xffffffffu, mx0, 2));
            mx1 = fmaxf(mx1, __shfl_xor_sync(0xffffffffu, mx1, 1));
            mx1 = fmaxf(mx1, __shfl_xor_sync(0xffffffffu, mx1, 2));
            float mn0 = fmaxf(m0, mx0), mn1 = fmaxf(m1, mx1);
            float sc0 = __expf(m0 - mn0), sc1 = __expf(m1 - mn1);
            m0 = mn0; m1 = mn1;
            float s0 = 0.f, s1 = 0.f;
#pragma unroll
            for (int nt = 0; nt < 8; nt++) {
                c[nt][0] = __expf(c[nt][0] - mn0); s0 += c[nt][0];
                c[nt][1] = __expf(c[nt][1] - mn0); s0 += c[nt][1];
                c[nt][2] = __expf(c[nt][2] - mn1); s1 += c[nt][2];
                c[nt][3] = __expf(c[nt][3] - mn1); s1 += c[nt][3];
            }
            s0 += __shfl_xor_sync(0xffffffffu, s0, 1);
            s0 += __shfl_xor_sync(0xffffffffu, s0, 2);
            s1 += __shfl_xor_sync(0xffffffffu, s1, 1);
            s1 += __shfl_xor_sync(0xffffffffu, s1, 2);
            l0 = l0 * sc0 + s0;
            l1 = l1 * sc1 + s1;
#pragma unroll
            for (int nt = 0; nt < 8; nt++) {
                o[nt][0] *= sc0; o[nt][1] *= sc0;
                o[nt][2] *= sc1; o[nt][3] *= sc1;
            }

            // -------- P -> A-fragments (register reuse, hi/lo) --------
            uint32_t ph[4][4], pl[4][4];
#pragma unroll
            for (int kt = 0; kt < 4; kt++) {
                split_pack(c[2 * kt][0],     c[2 * kt][1],     ph[kt][0], pl[kt][0]);
                split_pack(c[2 * kt][2],     c[2 * kt][3],     ph[kt][1], pl[kt][1]);
                split_pack(c[2 * kt + 1][0], c[2 * kt + 1][1], ph[kt][2], pl[kt][2]);
                split_pack(c[2 * kt + 1][2], c[2 * kt + 1][3], ph[kt][3], pl[kt][3]);
            }

            // -------- O += P.V --------
            const int vkey = ((lane >> 3) & 1) * 8 + (lane & 7);
            const int vcol = (lane >> 4) * 8;
#pragma unroll
            for (int ntp = 0; ntp < 4; ntp++) {
#pragma unroll
                for (int kt = 0; kt < 4; kt++) {
                    uint32_t vh[4], vl[4];
                    uint32_t va = smb + (uint32_t)(((kt * 16 + vkey) * LP +
                                                   ntp * 16 + vcol) * 2);
                    ldsm_x4_t(vh, va + VOFF_H);
                    ldsm_x4_t(vl, va + VOFF_L);
                    mma16816(o[2 * ntp],     ph[kt], vh);
                    mma16816(o[2 * ntp],     ph[kt], vl);
                    mma16816(o[2 * ntp],     pl[kt], vh);
                    mma16816(o[2 * ntp + 1], ph[kt], vh + 2);
                    mma16816(o[2 * ntp + 1], ph[kt], vl + 2);
                    mma16816(o[2 * ntp + 1], pl[kt], vh + 2);
                }
            }
        }
        __syncthreads();
    }

    // -------- normalize + store --------
    {
        float inv0 = 1.0f / l0, inv1 = 1.0f / l1;
        const int cbase = hoff + 2 * (lane & 3);
        float* d0 = outg + (size_t)r0g * DMODEL;
        float* d1 = outg + (size_t)(r0g + 8) * DMODEL;
#pragma unroll
        for (int nt = 0; nt < 8; nt++) {
            float2 v0 = make_float2(o[nt][0] * inv0, o[nt][1] * inv0);
            float2 v1 = make_float2(o[nt][2] * inv1, o[nt][3] * inv1);
            *reinterpret_cast<float2*>(d0 + cbase + nt * 8) = v0;
            *reinterpret_cast<float2*>(d1 + cbase + nt * 8) = v1;
        }
    }
}

// ---------------------------------------------------------------------------
extern "C" void kernel_launch(void* const* d_in, const int* in_sizes, int n_in,
                              void* d_out, int out_size)
{
    const float* x  = (const float*)d_in[0];
    const float* Wq = (const float*)d_in[1];
    const float* Wk = (const float*)d_in[2];
    const float* Wv = (const float*)d_in[3];
    const float* Wo = (const float*)d_in[4];
    const float* bo = (const float*)d_in[5];
    float* out = (float*)d_out;

    float *q, *k, *v, *at;
    __nv_bfloat16 *xh, *xl, *ath, *atl;
    __nv_bfloat16 *qh, *ql, *kh, *kl, *vh, *vl;
    __nv_bfloat16 *wqh, *wql, *wkh, *wkl, *wvh, *wvl, *woh, *wol;
    cudaGetSymbolAddress((void**)&q,  g_q);
    cudaGetSymbolAddress((void**)&k,  g_k);
    cudaGetSymbolAddress((void**)&v,  g_v);
    cudaGetSymbolAddress((void**)&at, g_at);
    cudaGetSymbolAddress((void**)&xh,  g_xh);
    cudaGetSymbolAddress((void**)&xl,  g_xl);
    cudaGetSymbolAddress((void**)&ath, g_ath);
    cudaGetSymbolAddress((void**)&atl, g_atl);
    cudaGetSymbolAddress((void**)&qh, g_qh);
    cudaGetSymbolAddress((void**)&ql, g_ql);
    cudaGetSymbolAddress((void**)&kh, g_kh);
    cudaGetSymbolAddress((void**)&kl, g_kl);
    cudaGetSymbolAddress((void**)&vh, g_vh);
    cudaGetSymbolAddress((void**)&vl, g_vl);
    cudaGetSymbolAddress((void**)&wqh, g_wqh);
    cudaGetSymbolAddress((void**)&wql, g_wql);
    cudaGetSymbolAddress((void**)&wkh, g_wkh);
    cudaGetSymbolAddress((void**)&wkl, g_wkl);
    cudaGetSymbolAddress((void**)&wvh, g_wvh);
    cudaGetSymbolAddress((void**)&wvl, g_wvl);
    cudaGetSymbolAddress((void**)&woh, g_woh);
    cudaGetSymbolAddress((void**)&wol, g_wol);

    cudaFuncSetAttribute(gemm_wmma,
                         cudaFuncAttributeMaxDynamicSharedMemorySize,
                         GEMM_SMEM);

    const int NSPLIT = SEQ * DMODEL / 1024;

    // prep: split x, transpose+split all weights
    split_kernel<<<NSPLIT, 256>>>(x, xh, xl, 1.0f);
    dim3 gw(DMODEL / 32, DMODEL / 32, 4);
    wsplit_kernel<<<gw, dim3(32, 8)>>>(Wq, Wk, Wv, Wo,
        wqh, wql, wkh, wkl, wvh, wvl, woh, wol);

    // QKV projections (tensor cores, double-buffered)
    dim3 g1(DMODEL / 128, SEQ / 128, 3);
    gemm_wmma<<<g1, 256, GEMM_SMEM>>>(xh, xl,
        wqh, wql, wkh, wkl, wvh, wvl, q, k, v);

    // pre-split Q (scaled by beta), K, V for attention
    split_kernel<<<NSPLIT, 256>>>(q, qh, ql, 0.125f);
    split_kernel<<<NSPLIT, 256>>>(k, kh, kl, 1.0f);
    split_kernel<<<NSPLIT, 256>>>(v, vh, vl, 1.0f);

    // causal flash attention (mma.sync, register-resident, 2 CTAs/SM)
    dim3 g2(SEQ / 128, HEADS);
    attn_mma<<<g2, 256>>>(qh, ql, kh, kl, vh, vl, at);

    // split attention output, then Wo projection
    split_kernel<<<NSPLIT, 256>>>(at, ath, atl, 1.0f);
    dim3 g3(DMODEL / 128, SEQ / 128, 1);
    gemm_wmma<<<g3, 256, GEMM_SMEM>>>(ath, atl,
        woh, wol, woh, wol, woh, wol, out, out, out);

    // bias epilogue
    bias_add<<<NSPLIT, 256>>>(out, bo);
}

// round 15
// speedup vs baseline: 2.4050x; 1.4496x over previous
#include <cuda_runtime.h>
#include <cuda_fp16.h>
#include <mma.h>
#include <cstdint>

using namespace nvcuda;

#define SEQ    4096
#define DMODEL 1024
#define HEADS  16
#define DHEAD  64

// ---------------- scratch (no cudaMalloc allowed) ----------------
__device__ float g_q[SEQ * DMODEL];
__device__ float g_k[SEQ * DMODEL];
__device__ float g_v[SEQ * DMODEL];
__device__ float g_at[SEQ * DMODEL];

__device__ __half g_xh[SEQ * DMODEL];
__device__ __half g_xl[SEQ * DMODEL];
__device__ __half g_ath[SEQ * DMODEL];
__device__ __half g_atl[SEQ * DMODEL];
__device__ __half g_qh[SEQ * DMODEL];
__device__ __half g_ql[SEQ * DMODEL];
__device__ __half g_k16[SEQ * DMODEL];
__device__ __half g_vh[SEQ * DMODEL];
__device__ __half g_vl[SEQ * DMODEL];
// transposed weights [N][K], fp16 single (B operand: rounded, not split)
__device__ __half g_wq16[DMODEL * DMODEL];
__device__ __half g_wk16[DMODEL * DMODEL];
__device__ __half g_wv16[DMODEL * DMODEL];
__device__ __half g_wo16[DMODEL * DMODEL];

__device__ __forceinline__ unsigned pkh2(float a, float b) {
    __half2 t = __floats2half2_rn(a, b);
    return *reinterpret_cast<unsigned*>(&t);
}

__device__ __forceinline__ uint32_t smem_u32(const void* p) {
    uint32_t a;
    asm("{ .reg .u64 t; cvta.to.shared.u64 t, %1; cvt.u32.u64 %0, t; }"
        : "=r"(a) : "l"(p));
    return a;
}

// ---------------- prep kernels ----------------
// fp32 -> fp16 hi/lo split (A operands)
__global__ void __launch_bounds__(256) splith_kernel(
    const float* __restrict__ src, __half* __restrict__ hi,
    __half* __restrict__ lo, float scale)
{
    int i = blockIdx.x * 256 + threadIdx.x;
    float4 v = reinterpret_cast<const float4*>(src)[i];
    v.x *= scale; v.y *= scale; v.z *= scale; v.w *= scale;
    __half h0 = __float2half_rn(v.x);
    __half h1 = __float2half_rn(v.y);
    __half h2 = __float2half_rn(v.z);
    __half h3 = __float2half_rn(v.w);
    uint2 hv, lv;
    __half2 p0 = {h0, h1}, p1 = {h2, h3};
    hv.x = *reinterpret_cast<unsigned*>(&p0);
    hv.y = *reinterpret_cast<unsigned*>(&p1);
    lv.x = pkh2(v.x - __half2float(h0), v.y - __half2float(h1));
    lv.y = pkh2(v.z - __half2float(h2), v.w - __half2float(h3));
    reinterpret_cast<uint2*>(hi)[i] = hv;
    reinterpret_cast<uint2*>(lo)[i] = lv;
}

// fp32 -> fp16 single round (B operands)
__global__ void __launch_bounds__(256) roundh_kernel(
    const float* __restrict__ src, __half* __restrict__ dst, float scale)
{
    int i = blockIdx.x * 256 + threadIdx.x;
    float4 v = reinterpret_cast<const float4*>(src)[i];
    uint2 hv;
    hv.x = pkh2(v.x * scale, v.y * scale);
    hv.y = pkh2(v.z * scale, v.w * scale);
    reinterpret_cast<uint2*>(dst)[i] = hv;
}

// W [K][N] row-major -> W^T [N][K] fp16 (rounded). z selects matrix.
__global__ void __launch_bounds__(256) wround_kernel(
    const float* __restrict__ W0, const float* __restrict__ W1,
    const float* __restrict__ W2, const float* __restrict__ W3,
    __half* H0, __half* H1, __half* H2, __half* H3)
{
    const int z = blockIdx.z;
    const float* W = (z == 0) ? W0 : (z == 1) ? W1 : (z == 2) ? W2 : W3;
    __half* H = (z == 0) ? H0 : (z == 1) ? H1 : (z == 2) ? H2 : H3;

    __shared__ float ts[32][33];
    const int n0 = blockIdx.x * 32, k0 = blockIdx.y * 32;
    const int tx = threadIdx.x, ty = threadIdx.y;
#pragma unroll
    for (int r = 0; r < 4; r++)
        ts[ty + 8 * r][tx] = W[(size_t)(k0 + ty + 8 * r) * DMODEL + n0 + tx];
    __syncthreads();
#pragma unroll
    for (int r = 0; r < 4; r++) {
        int n = n0 + ty + 8 * r;
        H[(size_t)n * DMODEL + k0 + tx] = __float2half_rn(ts[tx][ty + 8 * r]);
    }
}

// ---------------- WMMA fp16 2-pass GEMM, double-buffered ----------------
// C = (Ah+Al)[M][K] x B^T, B stored [N][K] fp16 single.
// 2 stages x (AH, AL, B), each 128x32 fp16, pitch LDM=40.
#define LDM 40
#define GS_ELEMS  (128 * LDM)            // 5120 halves per sub-tile
#define GS_STAGE  (3 * GS_ELEMS)         // 15360 halves per stage
#define GEMM_SMEM (2 * GS_STAGE * 2)     // 61440 bytes

__global__ void __launch_bounds__(256) gemm_wmma(
    const __half* __restrict__ Ah, const __half* __restrict__ Al,
    const __half* __restrict__ B0, const __half* __restrict__ B1,
    const __half* __restrict__ B2,
    float* C0, float* C1, float* C2)
{
    const int z = blockIdx.z;
    const __half* B = (z == 0) ? B0 : (z == 1) ? B1 : B2;
    float* C = (z == 0) ? C0 : (z == 1) ? C1 : C2;

    extern __shared__ __half gsm[];

    const int tid = threadIdx.x;
    const int wid = tid >> 5;
    const int wm = wid & 3;
    const int wn = wid >> 2;
    const int m0 = blockIdx.y * 128;
    const int n0 = blockIdx.x * 128;

    wmma::fragment<wmma::accumulator, 16, 16, 16, float> acc[2][4];
#pragma unroll
    for (int i = 0; i < 2; i++)
#pragma unroll
        for (int j = 0; j < 4; j++) wmma::fill_fragment(acc[i][j], 0.0f);

    const int r  = tid >> 2;           // 0..63
    const int ch = tid & 3;            // 8-elem chunk within 32

    const __half* gA[2] = {Ah + (size_t)m0 * DMODEL, Al + (size_t)m0 * DMODEL};
    const __half* gB = B + (size_t)n0 * DMODEL;

    uint4 rg[6];   // staged loads: [hf][AH, AL, B]

    // ---- prologue: load + store tile 0 ----
#pragma unroll
    for (int hf = 0; hf < 2; hf++) {
        const int row = r + hf * 64;
        const size_t go = (size_t)row * DMODEL + ch * 8;
        rg[hf * 3 + 0] = *reinterpret_cast<const uint4*>(gA[0] + go);
        rg[hf * 3 + 1] = *reinterpret_cast<const uint4*>(gA[1] + go);
        rg[hf * 3 + 2] = *reinterpret_cast<const uint4*>(gB + go);
    }
#pragma unroll
    for (int hf = 0; hf < 2; hf++) {
        const int so = (r + hf * 64) * LDM + ch * 8;
        *reinterpret_cast<uint4*>(&gsm[0 * GS_ELEMS + so]) = rg[hf * 3 + 0];
        *reinterpret_cast<uint4*>(&gsm[1 * GS_ELEMS + so]) = rg[hf * 3 + 1];
        *reinterpret_cast<uint4*>(&gsm[2 * GS_ELEMS + so]) = rg[hf * 3 + 2];
    }
    __syncthreads();

    for (int it = 0; it < 32; it++) {
        const bool has_next = (it < 31);
        if (has_next) {
            const int kc = (it + 1) * 32;
#pragma unroll
            for (int hf = 0; hf < 2; hf++) {
                const int row = r + hf * 64;
                const size_t go = (size_t)row * DMODEL + kc + ch * 8;
                rg[hf * 3 + 0] = *reinterpret_cast<const uint4*>(gA[0] + go);
                rg[hf * 3 + 1] = *reinterpret_cast<const uint4*>(gA[1] + go);
                rg[hf * 3 + 2] = *reinterpret_cast<const uint4*>(gB + go);
            }
        }

        __half* As0 = gsm + (it & 1) * GS_STAGE;
        __half* As1 = As0 + GS_ELEMS;
        __half* Bs  = As0 + 2 * GS_ELEMS;
#pragma unroll
        for (int ks = 0; ks < 32; ks += 16) {
            wmma::fragment<wmma::matrix_a, 16, 16, 16, __half,
                           wmma::row_major> ah[2], al[2];
#pragma unroll
            for (int i = 0; i < 2; i++) {
                wmma::load_matrix_sync(ah[i], &As0[(wm * 32 + 16 * i) * LDM + ks], LDM);
                wmma::load_matrix_sync(al[i], &As1[(wm * 32 + 16 * i) * LDM + ks], LDM);
            }
#pragma unroll
            for (int j = 0; j < 4; j++) {
                wmma::fragment<wmma::matrix_b, 16, 16, 16, __half,
                               wmma::col_major> bf;
                wmma::load_matrix_sync(bf, &Bs[(wn * 64 + 16 * j) * LDM + ks], LDM);
#pragma unroll
                for (int i = 0; i < 2; i++) {
                    wmma::mma_sync(acc[i][j], ah[i], bf, acc[i][j]);
                    wmma::mma_sync(acc[i][j], al[i], bf, acc[i][j]);
                }
            }
        }

        if (has_next) {
            __half* ns = gsm + ((it + 1) & 1) * GS_STAGE;
#pragma unroll
            for (int hf = 0; hf < 2; hf++) {
                const int so = (r + hf * 64) * LDM + ch * 8;
                *reinterpret_cast<uint4*>(&ns[0 * GS_ELEMS + so]) = rg[hf * 3 + 0];
                *reinterpret_cast<uint4*>(&ns[1 * GS_ELEMS + so]) = rg[hf * 3 + 1];
                *reinterpret_cast<uint4*>(&ns[2 * GS_ELEMS + so]) = rg[hf * 3 + 2];
            }
        }
        __syncthreads();
    }

#pragma unroll
    for (int i = 0; i < 2; i++)
#pragma unroll
        for (int j = 0; j < 4; j++)
            wmma::store_matrix_sync(
                &C[(size_t)(m0 + wm * 32 + 16 * i) * DMODEL + n0 + wn * 64 + 16 * j],
                acc[i][j], DMODEL, wmma::mem_row_major);
}

__global__ void __launch_bounds__(256) bias_add(
    float* __restrict__ out, const float* __restrict__ bo)
{
    int i = blockIdx.x * 256 + threadIdx.x;
    float4 v = reinterpret_cast<float4*>(out)[i];
    float4 b = *reinterpret_cast<const float4*>(&bo[(i * 4) & (DMODEL - 1)]);
    v.x += b.x; v.y += b.y; v.z += b.z; v.w += b.w;
    reinterpret_cast<float4*>(out)[i] = v;
}

// ---------------- mma.sync fp16 flash attention ----------------
// S = Qh.K + Ql.K (Q pre-split w/ beta; K single fp16).
// PV = P.Vh + P.Vl (P rounded single fp16; V pre-split).
// K/V tile smem: K + Vh + Vl = 27648 B. Q (128 rows = 18432 B per buffer) is
// staged Qh@0, Ql@18432 across the FULL 36864 B region (fixes R10 overlap).
#define LP 72            // fp16 pitch: rows 144B apart -> ldmatrix conflict-free
#define KOFF   0
#define VHOFF  9216
#define VLOFF  18432

__device__ __forceinline__ void ldsm_x4(uint32_t* r, uint32_t addr) {
    asm volatile("ldmatrix.sync.aligned.m8n8.x4.shared.b16 {%0,%1,%2,%3}, [%4];"
        : "=r"(r[0]), "=r"(r[1]), "=r"(r[2]), "=r"(r[3]) : "r"(addr));
}
__device__ __forceinline__ void ldsm_x4_t(uint32_t* r, uint32_t addr) {
    asm volatile("ldmatrix.sync.aligned.m8n8.x4.trans.shared.b16 {%0,%1,%2,%3}, [%4];"
        : "=r"(r[0]), "=r"(r[1]), "=r"(r[2]), "=r"(r[3]) : "r"(addr));
}
__device__ __forceinline__ void mma16816h(float* c, const uint32_t* a,
                                          const uint32_t* b) {
    asm volatile("mma.sync.aligned.m16n8k16.row.col.f32.f16.f16.f32 "
        "{%0,%1,%2,%3}, {%4,%5,%6,%7}, {%8,%9}, {%0,%1,%2,%3};"
        : "+f"(c[0]), "+f"(c[1]), "+f"(c[2]), "+f"(c[3])
        : "r"(a[0]), "r"(a[1]), "r"(a[2]), "r"(a[3]), "r"(b[0]), "r"(b[1]));
}

__global__ void __launch_bounds__(256, 2) attn_mma(
    const __half* __restrict__ qh_g, const __half* __restrict__ ql_g,
    const __half* __restrict__ k_g,
    const __half* __restrict__ vh_g, const __half* __restrict__ vl_g,
    float* __restrict__ outg)
{
    __shared__ char smc[36864];

    const int tid  = threadIdx.x;
    const int w    = tid >> 5;
    const int lane = tid & 31;
    const int h    = blockIdx.y;
    const int ib   = (int)(gridDim.x - 1u - blockIdx.x);  // heavy first
    const int row0 = ib * 128;
    const int hoff = h * DHEAD;
    const uint32_t smb = smem_u32(smc);

    // -------- stage Q: Qh @ 0 (18432 B), Ql @ 18432 (18432 B) --------
    {
#pragma unroll
        for (int u = 0; u < 4; u++) {
            const int unit = tid + 256 * u;          // 0..1023
            const int r = unit >> 3, ch = unit & 7;
            const size_t go = (size_t)(row0 + r) * DMODEL + hoff + ch * 8;
            *reinterpret_cast<uint4*>(smc + r * 144 + ch * 16) =
                *reinterpret_cast<const uint4*>(qh_g + go);
            *reinterpret_cast<uint4*>(smc + 18432 + r * 144 + ch * 16) =
                *reinterpret_cast<const uint4*>(ql_g + go);
        }
    }
    __syncthreads();

    // -------- persistent Q A-fragments (hi/lo, 16 rows per warp) --------
    uint32_t qh[4][4], ql[4][4];
    {
        const int qrow = w * 16 + (lane & 15);
        const int csel = (lane >> 4) * 8;
#pragma unroll
        for (int kt = 0; kt < 4; kt++) {
            uint32_t ah = smb + (uint32_t)((qrow * LP + kt * 16 + csel) * 2);
            ldsm_x4(qh[kt], ah);
            ldsm_x4(ql[kt], ah + 18432);
        }
    }
    __syncthreads();   // Q in registers before K/V overwrites the region

    float o[8][4];
#pragma unroll
    for (int nt = 0; nt < 8; nt++)
#pragma unroll
        for (int j = 0; j < 4; j++) o[nt][j] = 0.f;
    float m0 = -1e30f, m1 = -1e30f, l0 = 0.f, l1 = 0.f;

    const int r0g = row0 + w * 16 + (lane >> 2);  // this thread's first row
    const int jmax = 2 * ib + 1;

    for (int jb = 0; jb <= jmax; jb++) {
        // -------- load K, Vh, Vl tile: pure LDG.128 -> STS.128 --------
        {
#pragma unroll
            for (int u = 0; u < 2; u++) {
                const int unit = tid + 256 * u;      // 0..511
                const int r = unit >> 3, ch = unit & 7;
                const size_t go = (size_t)(jb * 64 + r) * DMODEL + hoff + ch * 8;
                const int so = r * 144 + ch * 16;
                *reinterpret_cast<uint4*>(smc + KOFF + so) =
                    *reinterpret_cast<const uint4*>(k_g + go);
                *reinterpret_cast<uint4*>(smc + VHOFF + so) =
                    *reinterpret_cast<const uint4*>(vh_g + go);
                *reinterpret_cast<uint4*>(smc + VLOFF + so) =
                    *reinterpret_cast<const uint4*>(vl_g + go);
            }
        }
        __syncthreads();

        // warp entirely in the future of this key tile? (warp-uniform)
        if (jb * 64 <= row0 + w * 16 + 15) {
            // -------- S = Qh.K + Ql.K : 16x64 in registers --------
            float c[8][4];
#pragma unroll
            for (int nt = 0; nt < 8; nt++)
#pragma unroll
                for (int j = 0; j < 4; j++) c[nt][j] = 0.f;

            const int kkey = (lane >> 4) * 8 + (lane & 7);
            const int kcol = ((lane >> 3) & 1) * 8;
#pragma unroll
            for (int kt = 0; kt < 4; kt++) {
#pragma unroll
                for (int ntp = 0; ntp < 4; ntp++) {
                    uint32_t kb[4];
                    uint32_t ka = smb + (uint32_t)(((ntp * 16 + kkey) * LP +
                                                   kt * 16 + kcol) * 2);
                    ldsm_x4(kb, ka + KOFF);
                    mma16816h(c[2 * ntp],     qh[kt], kb);
                    mma16816h(c[2 * ntp],     ql[kt], kb);
                    mma16816h(c[2 * ntp + 1], qh[kt], kb + 2);
                    mma16816h(c[2 * ntp + 1], ql[kt], kb + 2);
                }
            }

            // -------- causal mask (only near/on diagonal) --------
            if (jb >= 2 * ib) {
#pragma unroll
                for (int nt = 0; nt < 8; nt++) {
                    int colg = jb * 64 + nt * 8 + 2 * (lane & 3);
                    if (colg     > r0g)     c[nt][0] = -1e30f;
                    if (colg + 1 > r0g)     c[nt][1] = -1e30f;
                    if (colg     > r0g + 8) c[nt][2] = -1e30f;
                    if (colg + 1 > r0g + 8) c[nt][3] = -1e30f;
                }
            }

            // -------- register online softmax (rows r0g, r0g+8) --------
            float mx0 = -1e30f, mx1 = -1e30f;
#pragma unroll
            for (int nt = 0; nt < 8; nt++) {
                mx0 = fmaxf(mx0, fmaxf(c[nt][0], c[nt][1]));
                mx1 = fmaxf(mx1, fmaxf(c[nt][2], c[nt][3]));
            }
            mx0 = fmaxf(mx0, __shfl_xor_sync(0xffffffffu, mx0, 1));
            mx0 = fmaxf(mx0, __shfl_xor_sync(0xffffffffu, mx0, 2));
            mx1 = fmaxf(mx1, __shfl_xor_sync(0xffffffffu, mx1, 1));
            mx1 = fmaxf(mx1, __shfl_xor_sync(0xffffffffu, mx1, 2));
            float mn0 = fmaxf(m0, mx0), mn1 = fmaxf(m1, mx1);
            float sc0 = __expf(m0 - mn0), sc1 = __expf(m1 - mn1);
            m0 = mn0; m1 = mn1;
            float s0 = 0.f, s1 = 0.f;
#pragma unroll
            for (int nt = 0; nt < 8; nt++) {
                c[nt][0] = __expf(c[nt][0] - mn0); s0 += c[nt][0];
                c[nt][1] = __expf(c[nt][1] - mn0); s0 += c[nt][1];
                c[nt][2] = __expf(c[nt][2] - mn1); s1 += c[nt][2];
                c[nt][3] = __expf(c[nt][3] - mn1); s1 += c[nt][3];
            }
            s0 += __shfl_xor_sync(0xffffffffu, s0, 1);
            s0 += __shfl_xor_sync(0xffffffffu, s0, 2);
            s1 += __shfl_xor_sync(0xffffffffu, s1, 1);
            s1 += __shfl_xor_sync(0xffffffffu, s1, 2);
            l0 = l0 * sc0 + s0;
            l1 = l1 * sc1 + s1;
#pragma unroll
            for (int nt = 0; nt < 8; nt++) {
                o[nt][0] *= sc0; o[nt][1] *= sc0;
                o[nt][2] *= sc1; o[nt][3] *= sc1;
            }

            // -------- P -> single fp16 A-fragments (register reuse) --------
            uint32_t ph[4][4];
#pragma unroll
            for (int kt = 0; kt < 4; kt++) {
                ph[kt][0] = pkh2(c[2 * kt][0],     c[2 * kt][1]);
                ph[kt][1] = pkh2(c[2 * kt][2],     c[2 * kt][3]);
                ph[kt][2] = pkh2(c[2 * kt + 1][0], c[2 * kt + 1][1]);
                ph[kt][3] = pkh2(c[2 * kt + 1][2], c[2 * kt + 1][3]);
            }

            // -------- O += P.Vh + P.Vl --------
            const int vkey = ((lane >> 3) & 1) * 8 + (lane & 7);
            const int vcol = (lane >> 4) * 8;
#pragma unroll
            for (int ntp = 0; ntp < 4; ntp++) {
#pragma unroll
                for (int kt = 0; kt < 4; kt++) {
                    uint32_t vh[4], vl[4];
                    uint32_t va = smb + (uint32_t)(((kt * 16 + vkey) * LP +
                                                   ntp * 16 + vcol) * 2);
                    ldsm_x4_t(vh, va + VHOFF);
                    ldsm_x4_t(vl, va + VLOFF);
                    mma16816h(o[2 * ntp],     ph[kt], vh);
                    mma16816h(o[2 * ntp],     ph[kt], vl);
                    mma16816h(o[2 * ntp + 1], ph[kt], vh + 2);
                    mma16816h(o[2 * ntp + 1], ph[kt], vl + 2);
                }
            }
        }
        __syncthreads();
    }

    // -------- normalize + store --------
    {
        float inv0 = 1.0f / l0, inv1 = 1.0f / l1;
        const int cbase = hoff + 2 * (lane & 3);
        float* d0 = outg + (size_t)r0g * DMODEL;
        float* d1 = outg + (size_t)(r0g + 8) * DMODEL;
#pragma unroll
        for (int nt = 0; nt < 8; nt++) {
            float2 v0 = make_float2(o[nt][0] * inv0, o[nt][1] * inv0);
            float2 v1 = make_float2(o[nt][2] * inv1, o[nt][3] * inv1);
            *reinterpret_cast<float2*>(d0 + cbase + nt * 8) = v0;
            *reinterpret_cast<float2*>(d1 + cbase + nt * 8) = v1;
        }
    }
}

// ---------------------------------------------------------------------------
extern "C" void kernel_launch(void* const* d_in, const int* in_sizes, int n_in,
                              void* d_out, int out_size)
{
    const float* x  = (const float*)d_in[0];
    const float* Wq = (const float*)d_in[1];
    const float* Wk = (const float*)d_in[2];
    const float* Wv = (const float*)d_in[3];
    const float* Wo = (const float*)d_in[4];
    const float* bo = (const float*)d_in[5];
    float* out = (float*)d_out;

    float *q, *k, *v, *at;
    __half *xh, *xl, *ath, *atl;
    __half *qh, *ql, *k16, *vh, *vl;
    __half *wq16, *wk16, *wv16, *wo16;
    cudaGetSymbolAddress((void**)&q,  g_q);
    cudaGetSymbolAddress((void**)&k,  g_k);
    cudaGetSymbolAddress((void**)&v,  g_v);
    cudaGetSymbolAddress((void**)&at, g_at);
    cudaGetSymbolAddress((void**)&xh,  g_xh);
    cudaGetSymbolAddress((void**)&xl,  g_xl);
    cudaGetSymbolAddress((void**)&ath, g_ath);
    cudaGetSymbolAddress((void**)&atl, g_atl);
    cudaGetSymbolAddress((void**)&qh,  g_qh);
    cudaGetSymbolAddress((void**)&ql,  g_ql);
    cudaGetSymbolAddress((void**)&k16, g_k16);
    cudaGetSymbolAddress((void**)&vh,  g_vh);
    cudaGetSymbolAddress((void**)&vl,  g_vl);
    cudaGetSymbolAddress((void**)&wq16, g_wq16);
    cudaGetSymbolAddress((void**)&wk16, g_wk16);
    cudaGetSymbolAddress((void**)&wv16, g_wv16);
    cudaGetSymbolAddress((void**)&wo16, g_wo16);

    cudaFuncSetAttribute(gemm_wmma,
                         cudaFuncAttributeMaxDynamicSharedMemorySize,
                         GEMM_SMEM);

    const int NV = SEQ * DMODEL / 1024;

    // prep: split x (fp16 hi/lo), transpose+round weights (fp16 single)
    splith_kernel<<<NV, 256>>>(x, xh, xl, 1.0f);
    dim3 gw(DMODEL / 32, DMODEL / 32, 4);
    wround_kernel<<<gw, dim3(32, 8)>>>(Wq, Wk, Wv, Wo,
                                       wq16, wk16, wv16, wo16);

    // QKV projections (fp16 2-pass tensor cores)
    dim3 g1(DMODEL / 128, SEQ / 128, 3);
    gemm_wmma<<<g1, 256, GEMM_SMEM>>>(xh, xl, wq16, wk16, wv16, q, k, v);

    // pre-split/round Q (w/ beta), K (single), V (split) for attention
    splith_kernel<<<NV, 256>>>(q, qh, ql, 0.125f);
    roundh_kernel<<<NV, 256>>>(k, k16, 1.0f);
    splith_kernel<<<NV, 256>>>(v, vh, vl, 1.0f);

    // causal flash attention (fp16 2-pass, register-resident, 2 CTAs/SM)
    dim3 g2(SEQ / 128, HEADS);
    attn_mma<<<g2, 256>>>(qh, ql, k16, vh, vl, at);

    // split attention output, then Wo projection
    splith_kernel<<<NV, 256>>>(at, ath, atl, 1.0f);
    dim3 g3(DMODEL / 128, SEQ / 128, 1);
    gemm_wmma<<<g3, 256, GEMM_SMEM>>>(ath, atl, wo16, wo16, wo16,
                                      out, out, out);

    // bias epilogue
    bias_add<<<NV, 256>>>(out, bo);
}

// round 16
// speedup vs baseline: 2.9519x; 1.2274x over previous
#include <cuda_runtime.h>
#include <cuda_fp16.h>
#include <mma.h>
#include <cstdint>

using namespace nvcuda;

#define SEQ    4096
#define DMODEL 1024
#define HEADS  16
#define DHEAD  64

// ---------------- scratch (no cudaMalloc allowed) ----------------
__device__ float g_q[SEQ * DMODEL];
__device__ float g_k[SEQ * DMODEL];
__device__ float g_v[SEQ * DMODEL];

__device__ __half g_xh[SEQ * DMODEL];
__device__ __half g_xl[SEQ * DMODEL];
__device__ __half g_ath[SEQ * DMODEL];
__device__ __half g_atl[SEQ * DMODEL];
__device__ __half g_q16[SEQ * DMODEL];
__device__ __half g_k16[SEQ * DMODEL];
__device__ __half g_v16[SEQ * DMODEL];
// transposed weights [N][K], fp16 single (B operand)
__device__ __half g_wq16[DMODEL * DMODEL];
__device__ __half g_wk16[DMODEL * DMODEL];
__device__ __half g_wv16[DMODEL * DMODEL];
__device__ __half g_wo16[DMODEL * DMODEL];

__device__ __forceinline__ unsigned pkh2(float a, float b) {
    __half2 t = __floats2half2_rn(a, b);
    return *reinterpret_cast<unsigned*>(&t);
}

__device__ __forceinline__ uint32_t smem_u32(const void* p) {
    uint32_t a;
    asm("{ .reg .u64 t; cvta.to.shared.u64 t, %1; cvt.u32.u64 %0, t; }"
        : "=r"(a) : "l"(p));
    return a;
}

// ---------------- prep kernels ----------------
// fp32 -> fp16 hi/lo split (A operands of GEMMs)
__global__ void __launch_bounds__(256) splith_kernel(
    const float* __restrict__ src, __half* __restrict__ hi,
    __half* __restrict__ lo, float scale)
{
    int i = blockIdx.x * 256 + threadIdx.x;
    float4 v = reinterpret_cast<const float4*>(src)[i];
    v.x *= scale; v.y *= scale; v.z *= scale; v.w *= scale;
    __half h0 = __float2half_rn(v.x);
    __half h1 = __float2half_rn(v.y);
    __half h2 = __float2half_rn(v.z);
    __half h3 = __float2half_rn(v.w);
    uint2 hv, lv;
    __half2 p0 = {h0, h1}, p1 = {h2, h3};
    hv.x = *reinterpret_cast<unsigned*>(&p0);
    hv.y = *reinterpret_cast<unsigned*>(&p1);
    lv.x = pkh2(v.x - __half2float(h0), v.y - __half2float(h1));
    lv.y = pkh2(v.z - __half2float(h2), v.w - __half2float(h3));
    reinterpret_cast<uint2*>(hi)[i] = hv;
    reinterpret_cast<uint2*>(lo)[i] = lv;
}

// fused fp32 -> fp16 single round of q (w/ beta), k, v in one launch
__global__ void __launch_bounds__(256) round3_kernel(
    const float* __restrict__ q, const float* __restrict__ k,
    const float* __restrict__ v,
    __half* __restrict__ q16, __half* __restrict__ k16,
    __half* __restrict__ v16)
{
    int i = blockIdx.x * 256 + threadIdx.x;
    float4 a = reinterpret_cast<const float4*>(q)[i];
    float4 b = reinterpret_cast<const float4*>(k)[i];
    float4 c = reinterpret_cast<const float4*>(v)[i];
    uint2 qa, kb, vc;
    qa.x = pkh2(a.x * 0.125f, a.y * 0.125f);
    qa.y = pkh2(a.z * 0.125f, a.w * 0.125f);
    kb.x = pkh2(b.x, b.y);  kb.y = pkh2(b.z, b.w);
    vc.x = pkh2(c.x, c.y);  vc.y = pkh2(c.z, c.w);
    reinterpret_cast<uint2*>(q16)[i] = qa;
    reinterpret_cast<uint2*>(k16)[i] = kb;
    reinterpret_cast<uint2*>(v16)[i] = vc;
}

// W [K][N] row-major -> W^T [N][K] fp16 (rounded). z selects matrix.
__global__ void __launch_bounds__(256) wround_kernel(
    const float* __restrict__ W0, const float* __restrict__ W1,
    const float* __restrict__ W2, const float* __restrict__ W3,
    __half* H0, __half* H1, __half* H2, __half* H3)
{
    const int z = blockIdx.z;
    const float* W = (z == 0) ? W0 : (z == 1) ? W1 : (z == 2) ? W2 : W3;
    __half* H = (z == 0) ? H0 : (z == 1) ? H1 : (z == 2) ? H2 : H3;

    __shared__ float ts[32][33];
    const int n0 = blockIdx.x * 32, k0 = blockIdx.y * 32;
    const int tx = threadIdx.x, ty = threadIdx.y;
#pragma unroll
    for (int r = 0; r < 4; r++)
        ts[ty + 8 * r][tx] = W[(size_t)(k0 + ty + 8 * r) * DMODEL + n0 + tx];
    __syncthreads();
#pragma unroll
    for (int r = 0; r < 4; r++) {
        int n = n0 + ty + 8 * r;
        H[(size_t)n * DMODEL + k0 + tx] = __float2half_rn(ts[tx][ty + 8 * r]);
    }
}

// ---------------- WMMA fp16 2-pass GEMM, double-buffered (R11) ----------------
#define LDM 40
#define GS_ELEMS  (128 * LDM)
#define GS_STAGE  (3 * GS_ELEMS)
#define GEMM_SMEM (2 * GS_STAGE * 2)     // 61440 bytes

__global__ void __launch_bounds__(256) gemm_wmma(
    const __half* __restrict__ Ah, const __half* __restrict__ Al,
    const __half* __restrict__ B0, const __half* __restrict__ B1,
    const __half* __restrict__ B2,
    float* C0, float* C1, float* C2)
{
    const int z = blockIdx.z;
    const __half* B = (z == 0) ? B0 : (z == 1) ? B1 : B2;
    float* C = (z == 0) ? C0 : (z == 1) ? C1 : C2;

    extern __shared__ __half gsm[];

    const int tid = threadIdx.x;
    const int wid = tid >> 5;
    const int wm = wid & 3;
    const int wn = wid >> 2;
    const int m0 = blockIdx.y * 128;
    const int n0 = blockIdx.x * 128;

    wmma::fragment<wmma::accumulator, 16, 16, 16, float> acc[2][4];
#pragma unroll
    for (int i = 0; i < 2; i++)
#pragma unroll
        for (int j = 0; j < 4; j++) wmma::fill_fragment(acc[i][j], 0.0f);

    const int r  = tid >> 2;
    const int ch = tid & 3;

    const __half* gA[2] = {Ah + (size_t)m0 * DMODEL, Al + (size_t)m0 * DMODEL};
    const __half* gB = B + (size_t)n0 * DMODEL;

    uint4 rg[6];

#pragma unroll
    for (int hf = 0; hf < 2; hf++) {
        const int row = r + hf * 64;
        const size_t go = (size_t)row * DMODEL + ch * 8;
        rg[hf * 3 + 0] = *reinterpret_cast<const uint4*>(gA[0] + go);
        rg[hf * 3 + 1] = *reinterpret_cast<const uint4*>(gA[1] + go);
        rg[hf * 3 + 2] = *reinterpret_cast<const uint4*>(gB + go);
    }
#pragma unroll
    for (int hf = 0; hf < 2; hf++) {
        const int so = (r + hf * 64) * LDM + ch * 8;
        *reinterpret_cast<uint4*>(&gsm[0 * GS_ELEMS + so]) = rg[hf * 3 + 0];
        *reinterpret_cast<uint4*>(&gsm[1 * GS_ELEMS + so]) = rg[hf * 3 + 1];
        *reinterpret_cast<uint4*>(&gsm[2 * GS_ELEMS + so]) = rg[hf * 3 + 2];
    }
    __syncthreads();

    for (int it = 0; it < 32; it++) {
        const bool has_next = (it < 31);
        if (has_next) {
            const int kc = (it + 1) * 32;
#pragma unroll
            for (int hf = 0; hf < 2; hf++) {
                const int row = r + hf * 64;
                const size_t go = (size_t)row * DMODEL + kc + ch * 8;
                rg[hf * 3 + 0] = *reinterpret_cast<const uint4*>(gA[0] + go);
                rg[hf * 3 + 1] = *reinterpret_cast<const uint4*>(gA[1] + go);
                rg[hf * 3 + 2] = *reinterpret_cast<const uint4*>(gB + go);
            }
        }

        __half* As0 = gsm + (it & 1) * GS_STAGE;
        __half* As1 = As0 + GS_ELEMS;
        __half* Bs  = As0 + 2 * GS_ELEMS;
#pragma unroll
        for (int ks = 0; ks < 32; ks += 16) {
            wmma::fragment<wmma::matrix_a, 16, 16, 16, __half,
                           wmma::row_major> ah[2], al[2];
#pragma unroll
            for (int i = 0; i < 2; i++) {
                wmma::load_matrix_sync(ah[i], &As0[(wm * 32 + 16 * i) * LDM + ks], LDM);
                wmma::load_matrix_sync(al[i], &As1[(wm * 32 + 16 * i) * LDM + ks], LDM);
            }
#pragma unroll
            for (int j = 0; j < 4; j++) {
                wmma::fragment<wmma::matrix_b, 16, 16, 16, __half,
                               wmma::col_major> bf;
                wmma::load_matrix_sync(bf, &Bs[(wn * 64 + 16 * j) * LDM + ks], LDM);
#pragma unroll
                for (int i = 0; i < 2; i++) {
                    wmma::mma_sync(acc[i][j], ah[i], bf, acc[i][j]);
                    wmma::mma_sync(acc[i][j], al[i], bf, acc[i][j]);
                }
            }
        }

        if (has_next) {
            __half* ns = gsm + ((it + 1) & 1) * GS_STAGE;
#pragma unroll
            for (int hf = 0; hf < 2; hf++) {
                const int so = (r + hf * 64) * LDM + ch * 8;
                *reinterpret_cast<uint4*>(&ns[0 * GS_ELEMS + so]) = rg[hf * 3 + 0];
                *reinterpret_cast<uint4*>(&ns[1 * GS_ELEMS + so]) = rg[hf * 3 + 1];
                *reinterpret_cast<uint4*>(&ns[2 * GS_ELEMS + so]) = rg[hf * 3 + 2];
            }
        }
        __syncthreads();
    }

#pragma unroll
    for (int i = 0; i < 2; i++)
#pragma unroll
        for (int j = 0; j < 4; j++)
            wmma::store_matrix_sync(
                &C[(size_t)(m0 + wm * 32 + 16 * i) * DMODEL + n0 + wn * 64 + 16 * j],
                acc[i][j], DMODEL, wmma::mem_row_major);
}

__global__ void __launch_bounds__(256) bias_add(
    float* __restrict__ out, const float* __restrict__ bo)
{
    int i = blockIdx.x * 256 + threadIdx.x;
    float4 v = reinterpret_cast<float4*>(out)[i];
    float4 b = *reinterpret_cast<const float4*>(&bo[(i * 4) & (DMODEL - 1)]);
    v.x += b.x; v.y += b.y; v.z += b.z; v.w += b.w;
    reinterpret_cast<float4*>(out)[i] = v;
}

// ---------------- mma.sync single-pass fp16 flash attention ----------------
// S = Q16.K16 (both rounded single; beta folded into Q). PV = P.V16.
// smem per tile: K (9216) + V (9216) = 18432 B. Q staged across the same
// region (128 rows x 144 B = 18432 B) before the key loop.
// Epilogue writes O directly as hi/lo fp16 (ath/atl) -- no fp32 round-trip.
#define LP 72
#define KOFF  0
#define VOFF  9216

__device__ __forceinline__ void ldsm_x4(uint32_t* r, uint32_t addr) {
    asm volatile("ldmatrix.sync.aligned.m8n8.x4.shared.b16 {%0,%1,%2,%3}, [%4];"
        : "=r"(r[0]), "=r"(r[1]), "=r"(r[2]), "=r"(r[3]) : "r"(addr));
}
__device__ __forceinline__ void ldsm_x4_t(uint32_t* r, uint32_t addr) {
    asm volatile("ldmatrix.sync.aligned.m8n8.x4.trans.shared.b16 {%0,%1,%2,%3}, [%4];"
        : "=r"(r[0]), "=r"(r[1]), "=r"(r[2]), "=r"(r[3]) : "r"(addr));
}
__device__ __forceinline__ void mma16816h(float* c, const uint32_t* a,
                                          const uint32_t* b) {
    asm volatile("mma.sync.aligned.m16n8k16.row.col.f32.f16.f16.f32 "
        "{%0,%1,%2,%3}, {%4,%5,%6,%7}, {%8,%9}, {%0,%1,%2,%3};"
        : "+f"(c[0]), "+f"(c[1]), "+f"(c[2]), "+f"(c[3])
        : "r"(a[0]), "r"(a[1]), "r"(a[2]), "r"(a[3]), "r"(b[0]), "r"(b[1]));
}

__global__ void __launch_bounds__(256, 2) attn_mma(
    const __half* __restrict__ q_g, const __half* __restrict__ k_g,
    const __half* __restrict__ v_g,
    __half* __restrict__ ath_g, __half* __restrict__ atl_g)
{
    __shared__ char smc[18432];

    const int tid  = threadIdx.x;
    const int w    = tid >> 5;
    const int lane = tid & 31;
    const int h    = blockIdx.y;
    const int ib   = (int)(gridDim.x - 1u - blockIdx.x);  // heavy first
    const int row0 = ib * 128;
    const int hoff = h * DHEAD;
    const uint32_t smb = smem_u32(smc);

    // -------- stage Q (single fp16, beta pre-folded): 128 rows --------
    {
#pragma unroll
        for (int u = 0; u < 4; u++) {
            const int unit = tid + 256 * u;          // 0..1023
            const int r = unit >> 3, ch = unit & 7;
            const size_t go = (size_t)(row0 + r) * DMODEL + hoff + ch * 8;
            *reinterpret_cast<uint4*>(smc + r * 144 + ch * 16) =
                *reinterpret_cast<const uint4*>(q_g + go);
        }
    }
    __syncthreads();

    // -------- persistent Q A-fragments (16 rows per warp) --------
    uint32_t qh[4][4];
    {
        const int qrow = w * 16 + (lane & 15);
        const int csel = (lane >> 4) * 8;
#pragma unroll
        for (int kt = 0; kt < 4; kt++)
            ldsm_x4(qh[kt], smb + (uint32_t)((qrow * LP + kt * 16 + csel) * 2));
    }
    __syncthreads();   // Q in registers before K/V overwrites the region

    float o[8][4];
#pragma unroll
    for (int nt = 0; nt < 8; nt++)
#pragma unroll
        for (int j = 0; j < 4; j++) o[nt][j] = 0.f;
    float m0 = -1e30f, m1 = -1e30f, l0 = 0.f, l1 = 0.f;

    const int r0g = row0 + w * 16 + (lane >> 2);
    const int jmax = 2 * ib + 1;

    for (int jb = 0; jb <= jmax; jb++) {
        // -------- load K, V tile: pure LDG.128 -> STS.128 --------
        {
#pragma unroll
            for (int u = 0; u < 2; u++) {
                const int unit = tid + 256 * u;      // 0..511
                const int r = unit >> 3, ch = unit & 7;
                const size_t go = (size_t)(jb * 64 + r) * DMODEL + hoff + ch * 8;
                const int so = r * 144 + ch * 16;
                *reinterpret_cast<uint4*>(smc + KOFF + so) =
                    *reinterpret_cast<const uint4*>(k_g + go);
                *reinterpret_cast<uint4*>(smc + VOFF + so) =
                    *reinterpret_cast<const uint4*>(v_g + go);
            }
        }
        __syncthreads();

        if (jb * 64 <= row0 + w * 16 + 15) {     // warp-uniform causal skip
            // -------- S = Q.K : 16x64 in registers --------
            float c[8][4];
#pragma unroll
            for (int nt = 0; nt < 8; nt++)
#pragma unroll
                for (int j = 0; j < 4; j++) c[nt][j] = 0.f;

            const int kkey = (lane >> 4) * 8 + (lane & 7);
            const int kcol = ((lane >> 3) & 1) * 8;
#pragma unroll
            for (int kt = 0; kt < 4; kt++) {
#pragma unroll
                for (int ntp = 0; ntp < 4; ntp++) {
                    uint32_t kb[4];
                    ldsm_x4(kb, smb + (uint32_t)(((ntp * 16 + kkey) * LP +
                                                 kt * 16 + kcol) * 2) + KOFF);
                    mma16816h(c[2 * ntp],     qh[kt], kb);
                    mma16816h(c[2 * ntp + 1], qh[kt], kb + 2);
                }
            }

            // -------- causal mask --------
            if (jb >= 2 * ib) {
#pragma unroll
                for (int nt = 0; nt < 8; nt++) {
                    int colg = jb * 64 + nt * 8 + 2 * (lane & 3);
                    if (colg     > r0g)     c[nt][0] = -1e30f;
                    if (colg + 1 > r0g)     c[nt][1] = -1e30f;
                    if (colg     > r0g + 8) c[nt][2] = -1e30f;
                    if (colg + 1 > r0g + 8) c[nt][3] = -1e30f;
                }
            }

            // -------- register online softmax --------
            float mx0 = -1e30f, mx1 = -1e30f;
#pragma unroll
            for (int nt = 0; nt < 8; nt++) {
                mx0 = fmaxf(mx0, fmaxf(c[nt][0], c[nt][1]));
                mx1 = fmaxf(mx1, fmaxf(c[nt][2], c[nt][3]));
            }
            mx0 = fmaxf(mx0, __shfl_xor_sync(0xffffffffu, mx0, 1));
            mx0 = fmaxf(mx0, __shfl_xor_sync(0xffffffffu, mx0, 2));
            mx1 = fmaxf(mx1, __shfl_xor_sync(0xffffffffu, mx1, 1));
            mx1 = fmaxf(mx1, __shfl_xor_sync(0xffffffffu, mx1, 2));
            float mn0 = fmaxf(m0, mx0), mn1 = fmaxf(m1, mx1);
            float sc0 = __expf(m0 - mn0), sc1 = __expf(m1 - mn1);
            m0 = mn0; m1 = mn1;
            float s0 = 0.f, s1 = 0.f;
#pragma unroll
            for (int nt = 0; nt < 8; nt++) {
                c[nt][0] = __expf(c[nt][0] - mn0); s0 += c[nt][0];
                c[nt][1] = __expf(c[nt][1] - mn0); s0 += c[nt][1];
                c[nt][2] = __expf(c[nt][2] - mn1); s1 += c[nt][2];
                c[nt][3] = __expf(c[nt][3] - mn1); s1 += c[nt][3];
            }
            s0 += __shfl_xor_sync(0xffffffffu, s0, 1);
            s0 += __shfl_xor_sync(0xffffffffu, s0, 2);
            s1 += __shfl_xor_sync(0xffffffffu, s1, 1);
            s1 += __shfl_xor_sync(0xffffffffu, s1, 2);
            l0 = l0 * sc0 + s0;
            l1 = l1 * sc1 + s1;
#pragma unroll
            for (int nt = 0; nt < 8; nt++) {
                o[nt][0] *= sc0; o[nt][1] *= sc0;
                o[nt][2] *= sc1; o[nt][3] *= sc1;
            }

            // -------- P -> single fp16 A-fragments --------
            uint32_t ph[4][4];
#pragma unroll
            for (int kt = 0; kt < 4; kt++) {
                ph[kt][0] = pkh2(c[2 * kt][0],     c[2 * kt][1]);
                ph[kt][1] = pkh2(c[2 * kt][2],     c[2 * kt][3]);
                ph[kt][2] = pkh2(c[2 * kt + 1][0], c[2 * kt + 1][1]);
                ph[kt][3] = pkh2(c[2 * kt + 1][2], c[2 * kt + 1][3]);
            }

            // -------- O += P.V --------
            const int vkey = ((lane >> 3) & 1) * 8 + (lane & 7);
            const int vcol = (lane >> 4) * 8;
#pragma unroll
            for (int ntp = 0; ntp < 4; ntp++) {
#pragma unroll
                for (int kt = 0; kt < 4; kt++) {
                    uint32_t vv[4];
                    ldsm_x4_t(vv, smb + (uint32_t)(((kt * 16 + vkey) * LP +
                                                   ntp * 16 + vcol) * 2) + VOFF);
                    mma16816h(o[2 * ntp],     ph[kt], vv);
                    mma16816h(o[2 * ntp + 1], ph[kt], vv + 2);
                }
            }
        }
        __syncthreads();
    }

    // -------- normalize + hi/lo split + store (fp16 x2, no fp32 pass) ------
    {
        float inv0 = 1.0f / l0, inv1 = 1.0f / l1;
        const int cbase = hoff + 2 * (lane & 3);
        __half* h0p = ath_g + (size_t)r0g * DMODEL;
        __half* h1p = ath_g + (size_t)(r0g + 8) * DMODEL;
        __half* l0p = atl_g + (size_t)r0g * DMODEL;
        __half* l1p = atl_g + (size_t)(r0g + 8) * DMODEL;
#pragma unroll
        for (int nt = 0; nt < 8; nt++) {
            float a0 = o[nt][0] * inv0, a1 = o[nt][1] * inv0;
            float b0 = o[nt][2] * inv1, b1 = o[nt][3] * inv1;
            __half ha0 = __float2half_rn(a0), ha1 = __float2half_rn(a1);
            __half hb0 = __float2half_rn(b0), hb1 = __float2half_rn(b1);
            __half2 hp0 = {ha0, ha1}, hp1 = {hb0, hb1};
            unsigned la = pkh2(a0 - __half2float(ha0), a1 - __half2float(ha1));
            unsigned lb = pkh2(b0 - __half2float(hb0), b1 - __half2float(hb1));
            *reinterpret_cast<unsigned*>(h0p + cbase + nt * 8) =
                *reinterpret_cast<unsigned*>(&hp0);
            *reinterpret_cast<unsigned*>(h1p + cbase + nt * 8) =
                *reinterpret_cast<unsigned*>(&hp1);
            *reinterpret_cast<unsigned*>(l0p + cbase + nt * 8) = la;
            *reinterpret_cast<unsigned*>(l1p + cbase + nt * 8) = lb;
        }
    }
}

// ---------------------------------------------------------------------------
extern "C" void kernel_launch(void* const* d_in, const int* in_sizes, int n_in,
                              void* d_out, int out_size)
{
    const float* x  = (const float*)d_in[0];
    const float* Wq = (const float*)d_in[1];
    const float* Wk = (const float*)d_in[2];
    const float* Wv = (const float*)d_in[3];
    const float* Wo = (const float*)d_in[4];
    const float* bo = (const float*)d_in[5];
    float* out = (float*)d_out;

    float *q, *k, *v;
    __half *xh, *xl, *ath, *atl;
    __half *q16, *k16, *v16;
    __half *wq16, *wk16, *wv16, *wo16;
    cudaGetSymbolAddress((void**)&q,  g_q);
    cudaGetSymbolAddress((void**)&k,  g_k);
    cudaGetSymbolAddress((void**)&v,  g_v);
    cudaGetSymbolAddress((void**)&xh,  g_xh);
    cudaGetSymbolAddress((void**)&xl,  g_xl);
    cudaGetSymbolAddress((void**)&ath, g_ath);
    cudaGetSymbolAddress((void**)&atl, g_atl);
    cudaGetSymbolAddress((void**)&q16, g_q16);
    cudaGetSymbolAddress((void**)&k16, g_k16);
    cudaGetSymbolAddress((void**)&v16, g_v16);
    cudaGetSymbolAddress((void**)&wq16, g_wq16);
    cudaGetSymbolAddress((void**)&wk16, g_wk16);
    cudaGetSymbolAddress((void**)&wv16, g_wv16);
    cudaGetSymbolAddress((void**)&wo16, g_wo16);

    cudaFuncSetAttribute(gemm_wmma,
                         cudaFuncAttributeMaxDynamicSharedMemorySize,
                         GEMM_SMEM);

    const int NV = SEQ * DMODEL / 1024;

    // prep: split x (fp16 hi/lo), transpose+round weights
    splith_kernel<<<NV, 256>>>(x, xh, xl, 1.0f);
    dim3 gw(DMODEL / 32, DMODEL / 32, 4);
    wround_kernel<<<gw, dim3(32, 8)>>>(Wq, Wk, Wv, Wo,
                                       wq16, wk16, wv16, wo16);

    // QKV projections (fp16 2-pass tensor cores)
    dim3 g1(DMODEL / 128, SEQ / 128, 3);
    gemm_wmma<<<g1, 256, GEMM_SMEM>>>(xh, xl, wq16, wk16, wv16, q, k, v);

    // fused single-round of q (beta), k, v
    round3_kernel<<<NV, 256>>>(q, k, v, q16, k16, v16);

    // causal flash attention (single-pass fp16) -> ath/atl directly
    dim3 g2(SEQ / 128, HEADS);
    attn_mma<<<g2, 256>>>(q16, k16, v16, ath, atl);

    // Wo projection (2-pass on attention output)
    dim3 g3(DMODEL / 128, SEQ / 128, 1);
    gemm_wmma<<<g3, 256, GEMM_SMEM>>>(ath, atl, wo16, wo16, wo16,
                                      out, out, out);

    // bias epilogue
    bias_add<<<NV, 256>>>(out, bo);
}

// round 17
// speedup vs baseline: 3.8535x; 1.3054x over previous
#include <cuda_runtime.h>
#include <cuda_fp16.h>
#include <mma.h>
#include <cstdint>

using namespace nvcuda;

#define SEQ    4096
#define DMODEL 1024
#define HEADS  16
#define DHEAD  64

// ---------------- scratch (no cudaMalloc allowed) ----------------
__device__ float g_q[SEQ * DMODEL];
__device__ float g_k[SEQ * DMODEL];
__device__ float g_v[SEQ * DMODEL];

__device__ __half g_x16[SEQ * DMODEL];
__device__ __half g_at16[SEQ * DMODEL];
__device__ __half g_q16[SEQ * DMODEL];
__device__ __half g_k16[SEQ * DMODEL];
__device__ __half g_v16[SEQ * DMODEL];
// transposed weights [N][K], fp16 single
__device__ __half g_wq16[DMODEL * DMODEL];
__device__ __half g_wk16[DMODEL * DMODEL];
__device__ __half g_wv16[DMODEL * DMODEL];
__device__ __half g_wo16[DMODEL * DMODEL];

__device__ __forceinline__ unsigned pkh2(float a, float b) {
    __half2 t = __floats2half2_rn(a, b);
    return *reinterpret_cast<unsigned*>(&t);
}

__device__ __forceinline__ uint32_t smem_u32(const void* p) {
    uint32_t a;
    asm("{ .reg .u64 t; cvta.to.shared.u64 t, %1; cvt.u32.u64 %0, t; }"
        : "=r"(a) : "l"(p));
    return a;
}

// ---------------- prep kernels ----------------
// fp32 -> fp16 single round
__global__ void __launch_bounds__(256) roundh_kernel(
    const float* __restrict__ src, __half* __restrict__ dst, float scale)
{
    int i = blockIdx.x * 256 + threadIdx.x;
    float4 v = reinterpret_cast<const float4*>(src)[i];
    uint2 hv;
    hv.x = pkh2(v.x * scale, v.y * scale);
    hv.y = pkh2(v.z * scale, v.w * scale);
    reinterpret_cast<uint2*>(dst)[i] = hv;
}

// fused fp32 -> fp16 single round of q (w/ beta), k, v in one launch
__global__ void __launch_bounds__(256) round3_kernel(
    const float* __restrict__ q, const float* __restrict__ k,
    const float* __restrict__ v,
    __half* __restrict__ q16, __half* __restrict__ k16,
    __half* __restrict__ v16)
{
    int i = blockIdx.x * 256 + threadIdx.x;
    float4 a = reinterpret_cast<const float4*>(q)[i];
    float4 b = reinterpret_cast<const float4*>(k)[i];
    float4 c = reinterpret_cast<const float4*>(v)[i];
    uint2 qa, kb, vc;
    qa.x = pkh2(a.x * 0.125f, a.y * 0.125f);
    qa.y = pkh2(a.z * 0.125f, a.w * 0.125f);
    kb.x = pkh2(b.x, b.y);  kb.y = pkh2(b.z, b.w);
    vc.x = pkh2(c.x, c.y);  vc.y = pkh2(c.z, c.w);
    reinterpret_cast<uint2*>(q16)[i] = qa;
    reinterpret_cast<uint2*>(k16)[i] = kb;
    reinterpret_cast<uint2*>(v16)[i] = vc;
}

// W [K][N] row-major -> W^T [N][K] fp16 (rounded). z selects matrix.
__global__ void __launch_bounds__(256) wround_kernel(
    const float* __restrict__ W0, const float* __restrict__ W1,
    const float* __restrict__ W2, const float* __restrict__ W3,
    __half* H0, __half* H1, __half* H2, __half* H3)
{
    const int z = blockIdx.z;
    const float* W = (z == 0) ? W0 : (z == 1) ? W1 : (z == 2) ? W2 : W3;
    __half* H = (z == 0) ? H0 : (z == 1) ? H1 : (z == 2) ? H2 : H3;

    __shared__ float ts[32][33];
    const int n0 = blockIdx.x * 32, k0 = blockIdx.y * 32;
    const int tx = threadIdx.x, ty = threadIdx.y;
#pragma unroll
    for (int r = 0; r < 4; r++)
        ts[ty + 8 * r][tx] = W[(size_t)(k0 + ty + 8 * r) * DMODEL + n0 + tx];
    __syncthreads();
#pragma unroll
    for (int r = 0; r < 4; r++) {
        int n = n0 + ty + 8 * r;
        H[(size_t)n * DMODEL + k0 + tx] = __float2half_rn(ts[tx][ty + 8 * r]);
    }
}

// ---------------- WMMA fp16 single-pass GEMM, double-buffered ----------------
// C = A[M][K] x B^T, both single fp16, B stored [N][K].
// 2 stages x (A, B), each 128x32 fp16, pitch LDM=40.
#define LDM 40
#define GS_ELEMS  (128 * LDM)
#define GS_STAGE  (2 * GS_ELEMS)
#define GEMM_SMEM (2 * GS_STAGE * 2)     // 40960 bytes

__global__ void __launch_bounds__(256) gemm_wmma(
    const __half* __restrict__ A,
    const __half* __restrict__ B0, const __half* __restrict__ B1,
    const __half* __restrict__ B2,
    float* C0, float* C1, float* C2)
{
    const int z = blockIdx.z;
    const __half* B = (z == 0) ? B0 : (z == 1) ? B1 : B2;
    float* C = (z == 0) ? C0 : (z == 1) ? C1 : C2;

    extern __shared__ __half gsm[];

    const int tid = threadIdx.x;
    const int wid = tid >> 5;
    const int wm = wid & 3;
    const int wn = wid >> 2;
    const int m0 = blockIdx.y * 128;
    const int n0 = blockIdx.x * 128;

    wmma::fragment<wmma::accumulator, 16, 16, 16, float> acc[2][4];
#pragma unroll
    for (int i = 0; i < 2; i++)
#pragma unroll
        for (int j = 0; j < 4; j++) wmma::fill_fragment(acc[i][j], 0.0f);

    const int r  = tid >> 2;
    const int ch = tid & 3;

    const __half* gA = A + (size_t)m0 * DMODEL;
    const __half* gB = B + (size_t)n0 * DMODEL;

    uint4 rg[4];

#pragma unroll
    for (int hf = 0; hf < 2; hf++) {
        const int row = r + hf * 64;
        const size_t go = (size_t)row * DMODEL + ch * 8;
        rg[hf * 2 + 0] = *reinterpret_cast<const uint4*>(gA + go);
        rg[hf * 2 + 1] = *reinterpret_cast<const uint4*>(gB + go);
    }
#pragma unroll
    for (int hf = 0; hf < 2; hf++) {
        const int so = (r + hf * 64) * LDM + ch * 8;
        *reinterpret_cast<uint4*>(&gsm[0 * GS_ELEMS + so]) = rg[hf * 2 + 0];
        *reinterpret_cast<uint4*>(&gsm[1 * GS_ELEMS + so]) = rg[hf * 2 + 1];
    }
    __syncthreads();

    for (int it = 0; it < 32; it++) {
        const bool has_next = (it < 31);
        if (has_next) {
            const int kc = (it + 1) * 32;
#pragma unroll
            for (int hf = 0; hf < 2; hf++) {
                const int row = r + hf * 64;
                const size_t go = (size_t)row * DMODEL + kc + ch * 8;
                rg[hf * 2 + 0] = *reinterpret_cast<const uint4*>(gA + go);
                rg[hf * 2 + 1] = *reinterpret_cast<const uint4*>(gB + go);
            }
        }

        __half* As = gsm + (it & 1) * GS_STAGE;
        __half* Bs = As + GS_ELEMS;
#pragma unroll
        for (int ks = 0; ks < 32; ks += 16) {
            wmma::fragment<wmma::matrix_a, 16, 16, 16, __half,
                           wmma::row_major> af[2];
#pragma unroll
            for (int i = 0; i < 2; i++)
                wmma::load_matrix_sync(af[i], &As[(wm * 32 + 16 * i) * LDM + ks], LDM);
#pragma unroll
            for (int j = 0; j < 4; j++) {
                wmma::fragment<wmma::matrix_b, 16, 16, 16, __half,
                               wmma::col_major> bf;
                wmma::load_matrix_sync(bf, &Bs[(wn * 64 + 16 * j) * LDM + ks], LDM);
#pragma unroll
                for (int i = 0; i < 2; i++)
                    wmma::mma_sync(acc[i][j], af[i], bf, acc[i][j]);
            }
        }

        if (has_next) {
            __half* ns = gsm + ((it + 1) & 1) * GS_STAGE;
#pragma unroll
            for (int hf = 0; hf < 2; hf++) {
                const int so = (r + hf * 64) * LDM + ch * 8;
                *reinterpret_cast<uint4*>(&ns[0 * GS_ELEMS + so]) = rg[hf * 2 + 0];
                *reinterpret_cast<uint4*>(&ns[1 * GS_ELEMS + so]) = rg[hf * 2 + 1];
            }
        }
        __syncthreads();
    }

#pragma unroll
    for (int i = 0; i < 2; i++)
#pragma unroll
        for (int j = 0; j < 4; j++)
            wmma::store_matrix_sync(
                &C[(size_t)(m0 + wm * 32 + 16 * i) * DMODEL + n0 + wn * 64 + 16 * j],
                acc[i][j], DMODEL, wmma::mem_row_major);
}

__global__ void __launch_bounds__(256) bias_add(
    float* __restrict__ out, const float* __restrict__ bo)
{
    int i = blockIdx.x * 256 + threadIdx.x;
    float4 v = reinterpret_cast<float4*>(out)[i];
    float4 b = *reinterpret_cast<const float4*>(&bo[(i * 4) & (DMODEL - 1)]);
    v.x += b.x; v.y += b.y; v.z += b.z; v.w += b.w;
    reinterpret_cast<float4*>(out)[i] = v;
}

// ---------------- mma.sync single-pass fp16 flash attention (R12) ----------
// S = Q16.K16 (beta folded into Q). PV = P.V16. Output written as single
// fp16 at16 (consumed by the single-pass Wo GEMM).
#define LP 72
#define KOFF  0
#define VOFF  9216

__device__ __forceinline__ void ldsm_x4(uint32_t* r, uint32_t addr) {
    asm volatile("ldmatrix.sync.aligned.m8n8.x4.shared.b16 {%0,%1,%2,%3}, [%4];"
        : "=r"(r[0]), "=r"(r[1]), "=r"(r[2]), "=r"(r[3]) : "r"(addr));
}
__device__ __forceinline__ void ldsm_x4_t(uint32_t* r, uint32_t addr) {
    asm volatile("ldmatrix.sync.aligned.m8n8.x4.trans.shared.b16 {%0,%1,%2,%3}, [%4];"
        : "=r"(r[0]), "=r"(r[1]), "=r"(r[2]), "=r"(r[3]) : "r"(addr));
}
__device__ __forceinline__ void mma16816h(float* c, const uint32_t* a,
                                          const uint32_t* b) {
    asm volatile("mma.sync.aligned.m16n8k16.row.col.f32.f16.f16.f32 "
        "{%0,%1,%2,%3}, {%4,%5,%6,%7}, {%8,%9}, {%0,%1,%2,%3};"
        : "+f"(c[0]), "+f"(c[1]), "+f"(c[2]), "+f"(c[3])
        : "r"(a[0]), "r"(a[1]), "r"(a[2]), "r"(a[3]), "r"(b[0]), "r"(b[1]));
}

__global__ void __launch_bounds__(256, 2) attn_mma(
    const __half* __restrict__ q_g, const __half* __restrict__ k_g,
    const __half* __restrict__ v_g, __half* __restrict__ at_g)
{
    __shared__ char smc[18432];

    const int tid  = threadIdx.x;
    const int w    = tid >> 5;
    const int lane = tid & 31;
    const int h    = blockIdx.y;
    const int ib   = (int)(gridDim.x - 1u - blockIdx.x);  // heavy first
    const int row0 = ib * 128;
    const int hoff = h * DHEAD;
    const uint32_t smb = smem_u32(smc);

    // -------- stage Q (single fp16, beta pre-folded): 128 rows --------
    {
#pragma unroll
        for (int u = 0; u < 4; u++) {
            const int unit = tid + 256 * u;
            const int r = unit >> 3, ch = unit & 7;
            const size_t go = (size_t)(row0 + r) * DMODEL + hoff + ch * 8;
            *reinterpret_cast<uint4*>(smc + r * 144 + ch * 16) =
                *reinterpret_cast<const uint4*>(q_g + go);
        }
    }
    __syncthreads();

    uint32_t qh[4][4];
    {
        const int qrow = w * 16 + (lane & 15);
        const int csel = (lane >> 4) * 8;
#pragma unroll
        for (int kt = 0; kt < 4; kt++)
            ldsm_x4(qh[kt], smb + (uint32_t)((qrow * LP + kt * 16 + csel) * 2));
    }
    __syncthreads();

    float o[8][4];
#pragma unroll
    for (int nt = 0; nt < 8; nt++)
#pragma unroll
        for (int j = 0; j < 4; j++) o[nt][j] = 0.f;
    float m0 = -1e30f, m1 = -1e30f, l0 = 0.f, l1 = 0.f;

    const int r0g = row0 + w * 16 + (lane >> 2);
    const int jmax = 2 * ib + 1;

    for (int jb = 0; jb <= jmax; jb++) {
        {
#pragma unroll
            for (int u = 0; u < 2; u++) {
                const int unit = tid + 256 * u;
                const int r = unit >> 3, ch = unit & 7;
                const size_t go = (size_t)(jb * 64 + r) * DMODEL + hoff + ch * 8;
                const int so = r * 144 + ch * 16;
                *reinterpret_cast<uint4*>(smc + KOFF + so) =
                    *reinterpret_cast<const uint4*>(k_g + go);
                *reinterpret_cast<uint4*>(smc + VOFF + so) =
                    *reinterpret_cast<const uint4*>(v_g + go);
            }
        }
        __syncthreads();

        if (jb * 64 <= row0 + w * 16 + 15) {
            float c[8][4];
#pragma unroll
            for (int nt = 0; nt < 8; nt++)
#pragma unroll
                for (int j = 0; j < 4; j++) c[nt][j] = 0.f;

            const int kkey = (lane >> 4) * 8 + (lane & 7);
            const int kcol = ((lane >> 3) & 1) * 8;
#pragma unroll
            for (int kt = 0; kt < 4; kt++) {
#pragma unroll
                for (int ntp = 0; ntp < 4; ntp++) {
                    uint32_t kb[4];
                    ldsm_x4(kb, smb + (uint32_t)(((ntp * 16 + kkey) * LP +
                                                 kt * 16 + kcol) * 2) + KOFF);
                    mma16816h(c[2 * ntp],     qh[kt], kb);
                    mma16816h(c[2 * ntp + 1], qh[kt], kb + 2);
                }
            }

            if (jb >= 2 * ib) {
#pragma unroll
                for (int nt = 0; nt < 8; nt++) {
                    int colg = jb * 64 + nt * 8 + 2 * (lane & 3);
                    if (colg     > r0g)     c[nt][0] = -1e30f;
                    if (colg + 1 > r0g)     c[nt][1] = -1e30f;
                    if (colg     > r0g + 8) c[nt][2] = -1e30f;
                    if (colg + 1 > r0g + 8) c[nt][3] = -1e30f;
                }
            }

            float mx0 = -1e30f, mx1 = -1e30f;
#pragma unroll
            for (int nt = 0; nt < 8; nt++) {
                mx0 = fmaxf(mx0, fmaxf(c[nt][0], c[nt][1]));
                mx1 = fmaxf(mx1, fmaxf(c[nt][2], c[nt][3]));
            }
            mx0 = fmaxf(mx0, __shfl_xor_sync(0xffffffffu, mx0, 1));
            mx0 = fmaxf(mx0, __shfl_xor_sync(0xffffffffu, mx0, 2));
            mx1 = fmaxf(mx1, __shfl_xor_sync(0xffffffffu, mx1, 1));
            mx1 = fmaxf(mx1, __shfl_xor_sync(0xffffffffu, mx1, 2));
            float mn0 = fmaxf(m0, mx0), mn1 = fmaxf(m1, mx1);
            float sc0 = __expf(m0 - mn0), sc1 = __expf(m1 - mn1);
            m0 = mn0; m1 = mn1;
            float s0 = 0.f, s1 = 0.f;
#pragma unroll
            for (int nt = 0; nt < 8; nt++) {
                c[nt][0] = __expf(c[nt][0] - mn0); s0 += c[nt][0];
                c[nt][1] = __expf(c[nt][1] - mn0); s0 += c[nt][1];
                c[nt][2] = __expf(c[nt][2] - mn1); s1 += c[nt][2];
                c[nt][3] = __expf(c[nt][3] - mn1); s1 += c[nt][3];
            }
            s0 += __shfl_xor_sync(0xffffffffu, s0, 1);
            s0 += __shfl_xor_sync(0xffffffffu, s0, 2);
            s1 += __shfl_xor_sync(0xffffffffu, s1, 1);
            s1 += __shfl_xor_sync(0xffffffffu, s1, 2);
            l0 = l0 * sc0 + s0;
            l1 = l1 * sc1 + s1;
#pragma unroll
            for (int nt = 0; nt < 8; nt++) {
                o[nt][0] *= sc0; o[nt][1] *= sc0;
                o[nt][2] *= sc1; o[nt][3] *= sc1;
            }

            uint32_t ph[4][4];
#pragma unroll
            for (int kt = 0; kt < 4; kt++) {
                ph[kt][0] = pkh2(c[2 * kt][0],     c[2 * kt][1]);
                ph[kt][1] = pkh2(c[2 * kt][2],     c[2 * kt][3]);
                ph[kt][2] = pkh2(c[2 * kt + 1][0], c[2 * kt + 1][1]);
                ph[kt][3] = pkh2(c[2 * kt + 1][2], c[2 * kt + 1][3]);
            }

            const int vkey = ((lane >> 3) & 1) * 8 + (lane & 7);
            const int vcol = (lane >> 4) * 8;
#pragma unroll
            for (int ntp = 0; ntp < 4; ntp++) {
#pragma unroll
                for (int kt = 0; kt < 4; kt++) {
                    uint32_t vv[4];
                    ldsm_x4_t(vv, smb + (uint32_t)(((kt * 16 + vkey) * LP +
                                                   ntp * 16 + vcol) * 2) + VOFF);
                    mma16816h(o[2 * ntp],     ph[kt], vv);
                    mma16816h(o[2 * ntp + 1], ph[kt], vv + 2);
                }
            }
        }
        __syncthreads();
    }

    // -------- normalize + round to fp16 + store --------
    {
        float inv0 = 1.0f / l0, inv1 = 1.0f / l1;
        const int cbase = hoff + 2 * (lane & 3);
        __half* d0 = at_g + (size_t)r0g * DMODEL;
        __half* d1 = at_g + (size_t)(r0g + 8) * DMODEL;
#pragma unroll
        for (int nt = 0; nt < 8; nt++) {
            unsigned p0 = pkh2(o[nt][0] * inv0, o[nt][1] * inv0);
            unsigned p1 = pkh2(o[nt][2] * inv1, o[nt][3] * inv1);
            *reinterpret_cast<unsigned*>(d0 + cbase + nt * 8) = p0;
            *reinterpret_cast<unsigned*>(d1 + cbase + nt * 8) = p1;
        }
    }
}

// ---------------------------------------------------------------------------
extern "C" void kernel_launch(void* const* d_in, const int* in_sizes, int n_in,
                              void* d_out, int out_size)
{
    const float* x  = (const float*)d_in[0];
    const float* Wq = (const float*)d_in[1];
    const float* Wk = (const float*)d_in[2];
    const float* Wv = (const float*)d_in[3];
    const float* Wo = (const float*)d_in[4];
    const float* bo = (const float*)d_in[5];
    float* out = (float*)d_out;

    float *q, *k, *v;
    __half *x16, *at16, *q16, *k16, *v16;
    __half *wq16, *wk16, *wv16, *wo16;
    cudaGetSymbolAddress((void**)&q,  g_q);
    cudaGetSymbolAddress((void**)&k,  g_k);
    cudaGetSymbolAddress((void**)&v,  g_v);
    cudaGetSymbolAddress((void**)&x16,  g_x16);
    cudaGetSymbolAddress((void**)&at16, g_at16);
    cudaGetSymbolAddress((void**)&q16, g_q16);
    cudaGetSymbolAddress((void**)&k16, g_k16);
    cudaGetSymbolAddress((void**)&v16, g_v16);
    cudaGetSymbolAddress((void**)&wq16, g_wq16);
    cudaGetSymbolAddress((void**)&wk16, g_wk16);
    cudaGetSymbolAddress((void**)&wv16, g_wv16);
    cudaGetSymbolAddress((void**)&wo16, g_wo16);

    cudaFuncSetAttribute(gemm_wmma,
                         cudaFuncAttributeMaxDynamicSharedMemorySize,
                         GEMM_SMEM);

    const int NV = SEQ * DMODEL / 1024;

    // prep: round x, transpose+round weights
    roundh_kernel<<<NV, 256>>>(x, x16, 1.0f);
    dim3 gw(DMODEL / 32, DMODEL / 32, 4);
    wround_kernel<<<gw, dim3(32, 8)>>>(Wq, Wk, Wv, Wo,
                                       wq16, wk16, wv16, wo16);

    // QKV projections (single-pass fp16 tensor cores)
    dim3 g1(DMODEL / 128, SEQ / 128, 3);
    gemm_wmma<<<g1, 256, GEMM_SMEM>>>(x16, wq16, wk16, wv16, q, k, v);

    // fused single-round of q (beta), k, v
    round3_kernel<<<NV, 256>>>(q, k, v, q16, k16, v16);

    // causal flash attention (single-pass fp16) -> at16
    dim3 g2(SEQ / 128, HEADS);
    attn_mma<<<g2, 256>>>(q16, k16, v16, at16);

    // Wo projection (single-pass on attention output)
    dim3 g3(DMODEL / 128, SEQ / 128, 1);
    gemm_wmma<<<g3, 256, GEMM_SMEM>>>(at16, wo16, wo16, wo16,
                                      out, out, out);

    // bias epilogue
    bias_add<<<NV, 256>>>(out, bo);
}